// round 7
// baseline (speedup 1.0000x reference)
#include <cuda_runtime.h>
#include <math.h>

#define BB 64
#define LL 200
#define HH 128
#define SS 64
#define EE 256
#define NBLK 2
#define MM (BB*LL)
#define KC 101
#define LDSSM 192
#define LDXZ (2*EE)

// TF32 round-to-nearest (matches tensor-core operand conversion; XLA default
// fp32 matmul/conv path on GPU = tf32 products, fp32 accumulation).
__device__ __forceinline__ float tf32r(float x) {
    float r;
    asm("cvt.rna.tf32.f32 %0, %1;" : "=f"(r) : "f"(x));
    return r;
}

// Scratch (device globals — no allocation allowed)
__device__ __align__(16) float g_x[MM*HH];
__device__ __align__(16) float g_u[MM*HH];
__device__ __align__(16) float g_xz[MM*LDXZ];
__device__ __align__(16) float g_xc[MM*EE];
__device__ __align__(16) float g_ssm[MM*LDSSM];   // [delta | dB | C]
__device__ __align__(16) float g_y[MM*EE];
__device__ __align__(16) float g_xsum[MM];
__device__ __align__(16) float g_s[MM];

// ---------------------------------------------------------------------------
__global__ void embed_kernel(const int* __restrict__ seqs,
                             const float* __restrict__ item_emb,
                             const float* __restrict__ pos_emb,
                             float* __restrict__ x) {
    int m = blockIdx.x, h = threadIdx.x;
    int l = m % LL;
    int id = seqs[m];
    float v = item_emb[(size_t)id * HH + h] + pos_emb[l * HH + h];
    x[(size_t)m * HH + h] = (id != 0) ? v : 0.f;
}

// LayerNorm over H=128, one block per row (128 threads). TWO-PASS variance
// (subtract-then-square, matching the reference; no E[x^2]-m^2 cancellation).
__global__ void ln128_kernel(const float* __restrict__ x, float* __restrict__ u,
                             const float* __restrict__ g, const float* __restrict__ b) {
    int m = blockIdx.x, tid = threadIdx.x;
    float v = x[(size_t)m * HH + tid];
    __shared__ float sh1[4], sh2[4];
    float s1 = v;
#pragma unroll
    for (int o = 16; o; o >>= 1) s1 += __shfl_xor_sync(0xffffffffu, s1, o);
    if ((tid & 31) == 0) sh1[tid >> 5] = s1;
    __syncthreads();
    float mean = (sh1[0] + sh1[1] + sh1[2] + sh1[3]) * (1.f / HH);
    float d = v - mean;
    float s2 = d * d;
#pragma unroll
    for (int o = 16; o; o >>= 1) s2 += __shfl_xor_sync(0xffffffffu, s2, o);
    if ((tid & 31) == 0) sh2[tid >> 5] = s2;
    __syncthreads();
    float var = (sh2[0] + sh2[1] + sh2[2] + sh2[3]) * (1.f / HH);
    u[(size_t)m * HH + tid] = d * rsqrtf(var + 1e-5f) * g[tid] + b[tid];
}

// ---------------------------------------------------------------------------
// TF32-emulated GEMM: C[M,N] = A[M,K] @ W[K,N] + bias. Operands rounded to
// tf32 at smem store; fp32 FFMA accumulation (tf32 product is exact in fp32).
// epi==1: C = (resid + C + bias) * mask (residual in C).
__global__ void __launch_bounds__(256) gemm_kernel(
    const float* __restrict__ A, int lda,
    const float* __restrict__ W, int ldw,
    const float* __restrict__ bias,
    float* __restrict__ C, int ldc,
    int Kdim, int epi, const int* __restrict__ seqs)
{
    __shared__ __align__(16) float As[2][16 * 68];
    __shared__ __align__(16) float Ws[2][16 * 64];
    int tid = threadIdx.x;
    int m0 = blockIdx.y << 6, n0 = blockIdx.x << 6;
    int tx = tid & 15, ty = tid >> 4;
    int la_r = tid >> 2, la_k = (tid & 3) << 2;
    int lw_k = tid >> 4, lw_c = (tid & 15) << 2;
    const float* Ap = A + (size_t)(m0 + la_r) * lda + la_k;
    const float* Wp = W + (size_t)lw_k * ldw + n0 + lw_c;

    float4 ar = *(const float4*)Ap;
    float4 wr = *(const float4*)Wp;
    As[0][(la_k + 0) * 68 + la_r] = tf32r(ar.x);
    As[0][(la_k + 1) * 68 + la_r] = tf32r(ar.y);
    As[0][(la_k + 2) * 68 + la_r] = tf32r(ar.z);
    As[0][(la_k + 3) * 68 + la_r] = tf32r(ar.w);
    {
        float4 w4; w4.x = tf32r(wr.x); w4.y = tf32r(wr.y);
        w4.z = tf32r(wr.z); w4.w = tf32r(wr.w);
        *(float4*)&Ws[0][lw_k * 64 + lw_c] = w4;
    }
    __syncthreads();

    float acc[4][4];
#pragma unroll
    for (int i = 0; i < 4; i++)
#pragma unroll
        for (int j = 0; j < 4; j++) acc[i][j] = 0.f;

    int nk = Kdim >> 4;
    for (int kt = 0; kt < nk; kt++) {
        int cur = kt & 1;
        if (kt + 1 < nk) {
            ar = *(const float4*)(Ap + ((kt + 1) << 4));
            wr = *(const float4*)(Wp + (size_t)((kt + 1) << 4) * ldw);
        }
#pragma unroll
        for (int kk = 0; kk < 16; kk++) {
            float4 a4 = *(const float4*)&As[cur][kk * 68 + (ty << 2)];
            float4 b4 = *(const float4*)&Ws[cur][(kk << 6) + (tx << 2)];
            acc[0][0] += a4.x * b4.x; acc[0][1] += a4.x * b4.y; acc[0][2] += a4.x * b4.z; acc[0][3] += a4.x * b4.w;
            acc[1][0] += a4.y * b4.x; acc[1][1] += a4.y * b4.y; acc[1][2] += a4.y * b4.z; acc[1][3] += a4.y * b4.w;
            acc[2][0] += a4.z * b4.x; acc[2][1] += a4.z * b4.y; acc[2][2] += a4.z * b4.z; acc[2][3] += a4.z * b4.w;
            acc[3][0] += a4.w * b4.x; acc[3][1] += a4.w * b4.y; acc[3][2] += a4.w * b4.z; acc[3][3] += a4.w * b4.w;
        }
        if (kt + 1 < nk) {
            int nxt = cur ^ 1;
            As[nxt][(la_k + 0) * 68 + la_r] = tf32r(ar.x);
            As[nxt][(la_k + 1) * 68 + la_r] = tf32r(ar.y);
            As[nxt][(la_k + 2) * 68 + la_r] = tf32r(ar.z);
            As[nxt][(la_k + 3) * 68 + la_r] = tf32r(ar.w);
            float4 w4; w4.x = tf32r(wr.x); w4.y = tf32r(wr.y);
            w4.z = tf32r(wr.z); w4.w = tf32r(wr.w);
            *(float4*)&Ws[nxt][lw_k * 64 + lw_c] = w4;
        }
        __syncthreads();
    }

    int rowb = m0 + (ty << 2), colb = n0 + (tx << 2);
#pragma unroll
    for (int i = 0; i < 4; i++) {
        int m = rowb + i;
        float msk = 1.f;
        if (epi == 1) msk = (seqs[m] != 0) ? 1.f : 0.f;
#pragma unroll
        for (int j = 0; j < 4; j++) {
            float v = acc[i][j] + bias[colb + j];
            size_t off = (size_t)m * ldc + colb + j;
            if (epi == 1) v = (C[off] + v) * msk;
            C[off] = v;
        }
    }
}

// depthwise conv k=3 pad (1,1) + silu + row-sum. TF32 products (cudnn default).
__global__ void conv_kernel(const float* __restrict__ xz,
                            const float* __restrict__ cw, const float* __restrict__ cb,
                            float* __restrict__ xc, float* __restrict__ xsum) {
    int m = blockIdx.x, e = threadIdx.x;
    int l = m % LL;
    const float* xr = xz + (size_t)m * LDXZ;
    float w0 = tf32r(cw[e * 3]), w1 = tf32r(cw[e * 3 + 1]), w2 = tf32r(cw[e * 3 + 2]);
    float acc = tf32r(xr[e]) * w1;
    if (l > 0) acc += tf32r(xr[e - LDXZ]) * w0;
    if (l < LL - 1) acc += tf32r(xr[e + LDXZ]) * w2;
    acc += cb[e];
    float sv = acc / (1.f + expf(-acc));   // silu
    xc[(size_t)m * EE + e] = sv;
    float s = sv;
#pragma unroll
    for (int o = 16; o; o >>= 1) s += __shfl_xor_sync(0xffffffffu, s, o);
    __shared__ float sh[8];
    if ((e & 31) == 0) sh[e >> 5] = s;
    __syncthreads();
    if (e == 0) {
        float t = 0.f;
#pragma unroll
        for (int w = 0; w < 8; w++) t += sh[w];
        xsum[m] = t;
    }
}

// softplus(delta), dB = delta*B (in place, elementwise fp32). 64 thr/row.
__global__ void ssmpost_kernel(float* __restrict__ ssm) {
    int m = blockIdx.x, i = threadIdx.x;
    float* r = ssm + (size_t)m * LDSSM;
    float d = r[i];
    float sp = fmaxf(d, 0.f) + log1pf(expf(-fabsf(d)));
    float bm = r[SS + i];
    r[i] = sp;
    r[SS + i] = sp * bm;
}

// Sequential scan: g_t = clip(Ad_t @ g_{t-1} + dB_t * xs_t), s_t = dot(g_t, C_t)
// Reference's per-step einsums are TF32 matmuls: round exp(.), g, C to tf32,
// accumulate fp32. One CTA of 256 threads per batch, 4 threads per row i.
__global__ void __launch_bounds__(256) scan_kernel(
    const float* __restrict__ ssm, const float* __restrict__ xsum,
    const float* __restrict__ A_log, float* __restrict__ sout)
{
    int b = blockIdx.x, tid = threadIdx.x;
    __shared__ float A_sh[SS];
    __shared__ __align__(16) float gbuf[2][SS];   // tf32-rounded state
    __shared__ float psum[2][8];
    if (tid < SS) {
        float al = A_log[tid];
        al = fminf(fmaxf(al, -5.f), 5.f);
        A_sh[tid] = -expf(al);
        gbuf[0][tid] = 0.f;
    }
    __syncthreads();
    int i = tid >> 2, sub = tid & 3;
    float Aj[16];
#pragma unroll
    for (int q = 0; q < 16; q++) Aj[q] = A_sh[sub * 16 + q];

    const float* row = ssm + (size_t)b * LL * LDSSM;
    const float* xsr = xsum + b * LL;
    float nd = row[i], ndb = row[SS + i], nC = row[2 * SS + i], nxs = xsr[0];

    for (int t = 0; t < LL; t++) {
        float d = nd, db = ndb, Cv = nC, xs = nxs;
        if (t + 1 < LL) {               // prefetch next step
            const float* r2 = row + (t + 1) * LDSSM;
            nd = r2[i]; ndb = r2[SS + i]; nC = r2[2 * SS + i]; nxs = xsr[t + 1];
        }
        int par = t & 1;
        const float4* g4 = (const float4*)(gbuf[par] + sub * 16);
        float acc = 0.f;
#pragma unroll
        for (int q4 = 0; q4 < 4; q4++) {
            float4 gv = g4[q4];   // already tf32-rounded at store
            acc += tf32r(expf(fminf(fmaxf(d * Aj[q4 * 4 + 0], -10.f), 0.f))) * gv.x;
            acc += tf32r(expf(fminf(fmaxf(d * Aj[q4 * 4 + 1], -10.f), 0.f))) * gv.y;
            acc += tf32r(expf(fminf(fmaxf(d * Aj[q4 * 4 + 2], -10.f), 0.f))) * gv.z;
            acc += tf32r(expf(fminf(fmaxf(d * Aj[q4 * 4 + 3], -10.f), 0.f))) * gv.w;
        }
        acc += __shfl_xor_sync(0xffffffffu, acc, 1);
        acc += __shfl_xor_sync(0xffffffffu, acc, 2);
        if (sub == 0) {
            float gn = acc + db * xs;            // fp32 add (ref order)
            gn = fminf(fmaxf(gn, -100.f), 100.f);
            float gr = tf32r(gn);                // einsum operand rounding
            gbuf[par ^ 1][i] = gr;
            float p = gr * tf32r(Cv);            // 'bse,bs->be' in tf32
            p += __shfl_xor_sync(0x11111111u, p, 4);
            p += __shfl_xor_sync(0x11111111u, p, 8);
            p += __shfl_xor_sync(0x11111111u, p, 16);
            if ((tid & 31) == 0) psum[par][tid >> 5] = p;
        }
        __syncthreads();
        if (tid == 0) {
            float t2 = 0.f;
#pragma unroll
            for (int w = 0; w < 8; w++) t2 += psum[par][w];
            sout[b * LL + t] = t2;
        }
    }
}

// y = s + D*x ; inner LN over E (TWO-PASS variance — critical: y has common
// mode |s|~1 vs per-channel variation ~0.004; E[y^2]-m^2 cancels catastrophically);
// y *= silu(z). 256 thr/row.
__global__ void act_kernel(const float* __restrict__ xc, const float* __restrict__ s_in,
                           const float* __restrict__ xz, const float* __restrict__ D,
                           const float* __restrict__ ig, const float* __restrict__ ib,
                           float* __restrict__ y, int lastonly) {
    int m = lastonly ? (blockIdx.x * LL + (LL - 1)) : blockIdx.x;
    int e = threadIdx.x;
    float yv = s_in[m] + D[e] * xc[(size_t)m * EE + e];
    __shared__ float sh1[8], sh2[8];
    float s1 = yv;
#pragma unroll
    for (int o = 16; o; o >>= 1) s1 += __shfl_xor_sync(0xffffffffu, s1, o);
    if ((e & 31) == 0) sh1[e >> 5] = s1;
    __syncthreads();
    s1 = 0.f;
#pragma unroll
    for (int w = 0; w < 8; w++) s1 += sh1[w];
    float mean = s1 * (1.f / EE);
    float dcen = yv - mean;
    float s2 = dcen * dcen;
#pragma unroll
    for (int o = 16; o; o >>= 1) s2 += __shfl_xor_sync(0xffffffffu, s2, o);
    if ((e & 31) == 0) sh2[e >> 5] = s2;
    __syncthreads();
    s2 = 0.f;
#pragma unroll
    for (int w = 0; w < 8; w++) s2 += sh2[w];
    float var = s2 * (1.f / EE);
    float yn = dcen * rsqrtf(var + 1e-5f) * ig[e] + ib[e];
    float z = xz[(size_t)m * LDXZ + EE + e];
    y[(size_t)m * EE + e] = yn * (z / (1.f + expf(-z)));
}

// small projection for the last timestep rows only (block-2 z-half / C-cols)
__global__ void lastproj_kernel(const float* __restrict__ A, int lda,
                                const float* __restrict__ W, int ldw,
                                const float* __restrict__ bias,
                                float* __restrict__ C, int ldc,
                                int Kdim, int ncols, int coloff) {
    int b = blockIdx.x;
    int row = b * LL + (LL - 1);
    __shared__ float ush[EE];
    int tid = threadIdx.x;
    if (tid < Kdim) ush[tid] = tf32r(A[(size_t)row * lda + tid]);
    __syncthreads();
    for (int n = tid; n < ncols; n += blockDim.x) {
        float acc = 0.f;
        const float* wp = W + coloff + n;
#pragma unroll 4
        for (int k = 0; k < Kdim; k++) acc += ush[k] * tf32r(wp[(size_t)k * ldw]);
        C[(size_t)row * ldc + coloff + n] = acc + bias[coloff + n];
    }
}

// out-proj + residual + mask for last timestep rows (block 2)
__global__ void lastout_kernel(const float* __restrict__ y, const float* __restrict__ ow,
                               const float* __restrict__ ob, const int* __restrict__ seqs,
                               float* __restrict__ x) {
    int b = blockIdx.x, h = threadIdx.x;   // 128 threads
    int row = b * LL + (LL - 1);
    __shared__ float ysh[EE];
    ysh[h] = tf32r(y[(size_t)row * EE + h]);
    ysh[h + HH] = tf32r(y[(size_t)row * EE + h + HH]);
    __syncthreads();
    float acc = 0.f;
#pragma unroll 4
    for (int e = 0; e < EE; e++) acc += ysh[e] * tf32r(ow[e * HH + h]);
    float v = x[(size_t)row * HH + h] + (acc + ob[h]);
    x[(size_t)row * HH + h] = (seqs[row] != 0) ? v : 0.f;
}

// final LN (last timestep only, two-pass) + logits vs candidates (tf32 dot)
__global__ void final_kernel(const float* __restrict__ x, const int* __restrict__ idxs,
                             const float* __restrict__ item_emb,
                             const float* __restrict__ fg, const float* __restrict__ fb,
                             float* __restrict__ out) {
    int b = blockIdx.x, tid = threadIdx.x;   // 128 threads
    const float* xr = x + (size_t)(b * LL + LL - 1) * HH;
    float v = xr[tid];
    __shared__ float sh1[4], sh2[4];
    float s1 = v;
#pragma unroll
    for (int o = 16; o; o >>= 1) s1 += __shfl_xor_sync(0xffffffffu, s1, o);
    if ((tid & 31) == 0) sh1[tid >> 5] = s1;
    __syncthreads();
    float mean = (sh1[0] + sh1[1] + sh1[2] + sh1[3]) * (1.f / HH);
    float d = v - mean;
    float s2 = d * d;
#pragma unroll
    for (int o = 16; o; o >>= 1) s2 += __shfl_xor_sync(0xffffffffu, s2, o);
    if ((tid & 31) == 0) sh2[tid >> 5] = s2;
    __syncthreads();
    float var = (sh2[0] + sh2[1] + sh2[2] + sh2[3]) * (1.f / HH);
    __shared__ float xn[HH];
    xn[tid] = tf32r(d * rsqrtf(var + 1e-5f) * fg[tid] + fb[tid]);
    __syncthreads();
    int warp = tid >> 5, lane = tid & 31;
    for (int k = warp; k < KC; k += 4) {
        const float* er = item_emb + (size_t)idxs[b * KC + k] * HH;
        float p = xn[lane] * tf32r(er[lane]) + xn[lane + 32] * tf32r(er[lane + 32])
                + xn[lane + 64] * tf32r(er[lane + 64]) + xn[lane + 96] * tf32r(er[lane + 96]);
#pragma unroll
        for (int o = 16; o; o >>= 1) p += __shfl_xor_sync(0xffffffffu, p, o);
        if (lane == 0) out[b * KC + k] = p;
    }
}

// ---------------------------------------------------------------------------
extern "C" void kernel_launch(void* const* d_in, const int* in_sizes, int n_in,
                              void* d_out, int out_size) {
    (void)in_sizes; (void)n_in; (void)out_size;
    const int*   seqs     = (const int*)d_in[0];
    const int*   idxs     = (const int*)d_in[1];
    const float* item_emb = (const float*)d_in[2];
    const float* pos_emb  = (const float*)d_in[3];
    const float* blk_ln_g = (const float*)d_in[4];
    const float* blk_ln_b = (const float*)d_in[5];
    const float* in_w     = (const float*)d_in[6];
    const float* in_b     = (const float*)d_in[7];
    const float* conv_w   = (const float*)d_in[8];
    const float* conv_b   = (const float*)d_in[9];
    const float* xproj_w  = (const float*)d_in[10];
    const float* xproj_b  = (const float*)d_in[11];
    const float* A_log    = (const float*)d_in[12];
    const float* D_param  = (const float*)d_in[13];
    const float* out_w    = (const float*)d_in[14];
    const float* out_b    = (const float*)d_in[15];
    const float* inner_g  = (const float*)d_in[16];
    const float* inner_b  = (const float*)d_in[17];
    const float* final_g  = (const float*)d_in[18];
    const float* final_b  = (const float*)d_in[19];
    float* outp = (float*)d_out;

    float *px, *pu, *pxz, *pxc, *pssm, *py, *pxsum, *ps;
    cudaGetSymbolAddress((void**)&px, g_x);
    cudaGetSymbolAddress((void**)&pu, g_u);
    cudaGetSymbolAddress((void**)&pxz, g_xz);
    cudaGetSymbolAddress((void**)&pxc, g_xc);
    cudaGetSymbolAddress((void**)&pssm, g_ssm);
    cudaGetSymbolAddress((void**)&py, g_y);
    cudaGetSymbolAddress((void**)&pxsum, g_xsum);
    cudaGetSymbolAddress((void**)&ps, g_s);

    embed_kernel<<<MM, HH>>>(seqs, item_emb, pos_emb, px);

    for (int blk = 0; blk < NBLK; blk++) {
        const float* iw  = in_w    + (size_t)blk * HH * 2 * EE;
        const float* ibb = in_b    + blk * 2 * EE;
        const float* cw  = conv_w  + blk * EE * 3;
        const float* cb  = conv_b  + blk * EE;
        const float* xw  = xproj_w + (size_t)blk * EE * 3 * SS;
        const float* xb  = xproj_b + blk * 3 * SS;
        const float* al  = A_log   + blk * SS;
        const float* dp  = D_param + blk * EE;
        const float* ow  = out_w   + (size_t)blk * EE * HH;
        const float* ob  = out_b   + blk * HH;
        const float* ig  = inner_g + blk * EE;
        const float* ibn = inner_b + blk * EE;

        ln128_kernel<<<MM, HH>>>(px, pu, blk_ln_g + blk * HH, blk_ln_b + blk * HH);

        // in-projection: block 0 needs both x and z halves everywhere;
        // block 1 needs z only at the last timestep.
        int Nin = (blk == 0) ? (2 * EE) : EE;
        gemm_kernel<<<dim3(Nin / 64, MM / 64), 256>>>(pu, HH, iw, 2 * EE, ibb,
                                                      pxz, 2 * EE, HH, 0, nullptr);
        if (blk == 1)
            lastproj_kernel<<<BB, 256>>>(pu, HH, iw, 2 * EE, ibb, pxz, 2 * EE,
                                         HH, EE, EE);

        conv_kernel<<<MM, EE>>>(pxz, cw, cb, pxc, pxsum);

        // x-projection: block 0 needs delta,B,C; block 1 needs C only at last t.
        int Nxp = (blk == 0) ? (3 * SS) : (2 * SS);
        gemm_kernel<<<dim3(Nxp / 64, MM / 64), 256>>>(pxc, EE, xw, 3 * SS, xb,
                                                      pssm, LDSSM, EE, 0, nullptr);
        if (blk == 1)
            lastproj_kernel<<<BB, 256>>>(pxc, EE, xw, 3 * SS, xb, pssm, LDSSM,
                                         EE, SS, 2 * SS);

        ssmpost_kernel<<<MM, SS>>>(pssm);
        scan_kernel<<<BB, 256>>>(pssm, pxsum, al, ps);

        if (blk == 0) {
            act_kernel<<<MM, EE>>>(pxc, ps, pxz, dp, ig, ibn, py, 0);
            gemm_kernel<<<dim3(HH / 64, MM / 64), 256>>>(py, EE, ow, HH, ob,
                                                         px, HH, EE, 1, seqs);
        } else {
            act_kernel<<<BB, EE>>>(pxc, ps, pxz, dp, ig, ibn, py, 1);
            lastout_kernel<<<BB, HH>>>(py, ow, ob, seqs, px);
        }
    }

    final_kernel<<<BB, HH>>>(px, idxs, item_emb, final_g, final_b, outp);
}

// round 10
// speedup vs baseline: 1.1316x; 1.1316x over previous
#include <cuda_runtime.h>
#include <cstdint>
#include <math.h>

#define BB 64
#define LL 200
#define HH 128
#define SS 64
#define EE 256
#define NBLK 2
#define MM (BB*LL)
#define KC 101
#define LDSSM 192
#define LDXZ (2*EE)

// TF32 round-to-nearest (matches tensor-core operand conversion; XLA default
// fp32 matmul/conv path on GPU = tf32 products, fp32 accumulation).
__device__ __forceinline__ float tf32r(float x) {
    float r;
    asm("cvt.rna.tf32.f32 %0, %1;" : "=f"(r) : "f"(x));
    return r;
}

__device__ __forceinline__ void mma_tf32(float c[4],
    uint32_t a0, uint32_t a1, uint32_t a2, uint32_t a3,
    uint32_t b0, uint32_t b1) {
    asm volatile(
        "mma.sync.aligned.m16n8k8.row.col.f32.tf32.tf32.f32 "
        "{%0,%1,%2,%3}, {%4,%5,%6,%7}, {%8,%9}, {%0,%1,%2,%3};\n"
        : "+f"(c[0]), "+f"(c[1]), "+f"(c[2]), "+f"(c[3])
        : "r"(a0), "r"(a1), "r"(a2), "r"(a3), "r"(b0), "r"(b1));
}

// Scratch (device globals — no allocation allowed)
__device__ __align__(16) float g_x[MM*HH];
__device__ __align__(16) float g_u[MM*HH];
__device__ __align__(16) float g_xz[MM*LDXZ];
__device__ __align__(16) float g_xc[MM*EE];
__device__ __align__(16) float g_ssm[MM*LDSSM];   // [delta | dB | C]
__device__ __align__(16) float g_y[MM*EE];
__device__ __align__(16) float g_xsum[MM];
__device__ __align__(16) float g_s[MM];

// ---------------------------------------------------------------------------
__global__ void embed_kernel(const int* __restrict__ seqs,
                             const float* __restrict__ item_emb,
                             const float* __restrict__ pos_emb,
                             float* __restrict__ x) {
    int m = blockIdx.x, h = threadIdx.x;
    int l = m % LL;
    int id = seqs[m];
    float v = item_emb[(size_t)id * HH + h] + pos_emb[l * HH + h];
    x[(size_t)m * HH + h] = (id != 0) ? v : 0.f;
}

// LayerNorm over H=128, one block per row (128 threads). Two-pass variance.
__global__ void ln128_kernel(const float* __restrict__ x, float* __restrict__ u,
                             const float* __restrict__ g, const float* __restrict__ b) {
    int m = blockIdx.x, tid = threadIdx.x;
    float v = x[(size_t)m * HH + tid];
    __shared__ float sh1[4], sh2[4];
    float s1 = v;
#pragma unroll
    for (int o = 16; o; o >>= 1) s1 += __shfl_xor_sync(0xffffffffu, s1, o);
    if ((tid & 31) == 0) sh1[tid >> 5] = s1;
    __syncthreads();
    float mean = (sh1[0] + sh1[1] + sh1[2] + sh1[3]) * (1.f / HH);
    float d = v - mean;
    float s2 = d * d;
#pragma unroll
    for (int o = 16; o; o >>= 1) s2 += __shfl_xor_sync(0xffffffffu, s2, o);
    if ((tid & 31) == 0) sh2[tid >> 5] = s2;
    __syncthreads();
    float var = (sh2[0] + sh2[1] + sh2[2] + sh2[3]) * (1.f / HH);
    u[(size_t)m * HH + tid] = d * rsqrtf(var + 1e-5f) * g[tid] + b[tid];
}

// ---------------------------------------------------------------------------
// TF32 tensor-core GEMM: C[M,N] = A[M,K] @ W[K,N] + bias.
// BM=128, BN=64, BK=16; 8 warps (4m x 2n), warp tile 32x32 via m16n8k8 tf32.
// Operands tf32-rounded at smem store (same products as the emulated path).
// epi==1: C = (resid + C + bias) * mask (residual in C).
#define APAD 20
#define BPAD 72
__global__ void __launch_bounds__(256) gemm_tc_kernel(
    const float* __restrict__ A, int lda,
    const float* __restrict__ W, int ldw,
    const float* __restrict__ bias,
    float* __restrict__ C, int ldc,
    int Kdim, int epi, const int* __restrict__ seqs)
{
    __shared__ __align__(16) float As[2][128 * APAD];
    __shared__ __align__(16) float Ws[2][16 * BPAD];
    int tid = threadIdx.x;
    int m0 = blockIdx.y << 7, n0 = blockIdx.x << 6;
    int lane = tid & 31, wid = tid >> 5;
    int wm = (wid & 3) << 5;       // warp m offset: 0,32,64,96
    int wn = (wid >> 2) << 5;      // warp n offset: 0,32
    int g = lane >> 2, cq = lane & 3;

    // global load mapping
    int a_r = tid >> 2, a_q = tid & 3;          // A rows a_r and a_r+64, quad a_q
    int b_k = tid >> 4, b_q = tid & 15;         // B row b_k, quad b_q
    const float* ApBase = A + (size_t)(m0 + a_r) * lda + (a_q << 2);
    const float* WpBase = W + (size_t)b_k * ldw + n0 + (b_q << 2);

    float acc[2][4][4];
#pragma unroll
    for (int i = 0; i < 2; i++)
#pragma unroll
        for (int j = 0; j < 4; j++)
#pragma unroll
            for (int q = 0; q < 4; q++) acc[i][j][q] = 0.f;

    float4 av0 = *(const float4*)(ApBase);
    float4 av1 = *(const float4*)(ApBase + (size_t)64 * lda);
    float4 bv  = *(const float4*)(WpBase);
    {
        float4 t0, t1, tb;
        t0.x = tf32r(av0.x); t0.y = tf32r(av0.y); t0.z = tf32r(av0.z); t0.w = tf32r(av0.w);
        t1.x = tf32r(av1.x); t1.y = tf32r(av1.y); t1.z = tf32r(av1.z); t1.w = tf32r(av1.w);
        tb.x = tf32r(bv.x);  tb.y = tf32r(bv.y);  tb.z = tf32r(bv.z);  tb.w = tf32r(bv.w);
        *(float4*)&As[0][a_r * APAD + (a_q << 2)] = t0;
        *(float4*)&As[0][(a_r + 64) * APAD + (a_q << 2)] = t1;
        *(float4*)&Ws[0][b_k * BPAD + (b_q << 2)] = tb;
    }
    __syncthreads();

    int nk = Kdim >> 4;
    for (int kt = 0; kt < nk; kt++) {
        int cur = kt & 1;
        if (kt + 1 < nk) {
            av0 = *(const float4*)(ApBase + ((kt + 1) << 4));
            av1 = *(const float4*)(ApBase + (size_t)64 * lda + ((kt + 1) << 4));
            bv  = *(const float4*)(WpBase + (size_t)((kt + 1) << 4) * ldw);
        }
#pragma unroll
        for (int ks = 0; ks < 2; ks++) {
            int kk = ks << 3;
            uint32_t bf[4][2];
#pragma unroll
            for (int j = 0; j < 4; j++) {
                bf[j][0] = __float_as_uint(Ws[cur][(kk + cq) * BPAD + wn + (j << 3) + g]);
                bf[j][1] = __float_as_uint(Ws[cur][(kk + cq + 4) * BPAD + wn + (j << 3) + g]);
            }
#pragma unroll
            for (int i = 0; i < 2; i++) {
                const float* ab = &As[cur][(wm + (i << 4)) * APAD + kk + cq];
                uint32_t a0 = __float_as_uint(ab[g * APAD]);
                uint32_t a1 = __float_as_uint(ab[(g + 8) * APAD]);
                uint32_t a2 = __float_as_uint(ab[g * APAD + 4]);
                uint32_t a3 = __float_as_uint(ab[(g + 8) * APAD + 4]);
#pragma unroll
                for (int j = 0; j < 4; j++)
                    mma_tf32(acc[i][j], a0, a1, a2, a3, bf[j][0], bf[j][1]);
            }
        }
        if (kt + 1 < nk) {
            int nxt = cur ^ 1;
            float4 t0, t1, tb;
            t0.x = tf32r(av0.x); t0.y = tf32r(av0.y); t0.z = tf32r(av0.z); t0.w = tf32r(av0.w);
            t1.x = tf32r(av1.x); t1.y = tf32r(av1.y); t1.z = tf32r(av1.z); t1.w = tf32r(av1.w);
            tb.x = tf32r(bv.x);  tb.y = tf32r(bv.y);  tb.z = tf32r(bv.z);  tb.w = tf32r(bv.w);
            *(float4*)&As[nxt][a_r * APAD + (a_q << 2)] = t0;
            *(float4*)&As[nxt][(a_r + 64) * APAD + (a_q << 2)] = t1;
            *(float4*)&Ws[nxt][b_k * BPAD + (b_q << 2)] = tb;
        }
        __syncthreads();
    }

    // epilogue
#pragma unroll
    for (int i = 0; i < 2; i++) {
        int r0 = m0 + wm + (i << 4) + g;
        int r1 = r0 + 8;
        float msk0 = 1.f, msk1 = 1.f;
        if (epi == 1) {
            msk0 = (seqs[r0] != 0) ? 1.f : 0.f;
            msk1 = (seqs[r1] != 0) ? 1.f : 0.f;
        }
#pragma unroll
        for (int j = 0; j < 4; j++) {
            int col = n0 + wn + (j << 3) + (cq << 1);
            float b0 = bias[col], b1 = bias[col + 1];
            size_t o0 = (size_t)r0 * ldc + col;
            size_t o1 = (size_t)r1 * ldc + col;
            float v00 = acc[i][j][0] + b0, v01 = acc[i][j][1] + b1;
            float v10 = acc[i][j][2] + b0, v11 = acc[i][j][3] + b1;
            if (epi == 1) {
                v00 = (C[o0] + v00) * msk0; v01 = (C[o0 + 1] + v01) * msk0;
                v10 = (C[o1] + v10) * msk1; v11 = (C[o1 + 1] + v11) * msk1;
            }
            C[o0] = v00; C[o0 + 1] = v01;
            C[o1] = v10; C[o1 + 1] = v11;
        }
    }
}

// depthwise conv k=3 pad (1,1) + silu + row-sum. TF32 products.
__global__ void conv_kernel(const float* __restrict__ xz,
                            const float* __restrict__ cw, const float* __restrict__ cb,
                            float* __restrict__ xc, float* __restrict__ xsum) {
    int m = blockIdx.x, e = threadIdx.x;
    int l = m % LL;
    const float* xr = xz + (size_t)m * LDXZ;
    float w0 = tf32r(cw[e * 3]), w1 = tf32r(cw[e * 3 + 1]), w2 = tf32r(cw[e * 3 + 2]);
    float acc = tf32r(xr[e]) * w1;
    if (l > 0) acc += tf32r(xr[e - LDXZ]) * w0;
    if (l < LL - 1) acc += tf32r(xr[e + LDXZ]) * w2;
    acc += cb[e];
    float sv = acc / (1.f + expf(-acc));   // silu
    xc[(size_t)m * EE + e] = sv;
    float s = sv;
#pragma unroll
    for (int o = 16; o; o >>= 1) s += __shfl_xor_sync(0xffffffffu, s, o);
    __shared__ float sh[8];
    if ((e & 31) == 0) sh[e >> 5] = s;
    __syncthreads();
    if (e == 0) {
        float t = 0.f;
#pragma unroll
        for (int w = 0; w < 8; w++) t += sh[w];
        xsum[m] = t;
    }
}

// softplus(delta), dB = delta*B (in place, elementwise fp32). 64 thr/row.
__global__ void ssmpost_kernel(float* __restrict__ ssm) {
    int m = blockIdx.x, i = threadIdx.x;
    float* r = ssm + (size_t)m * LDSSM;
    float d = r[i];
    float sp = fmaxf(d, 0.f) + log1pf(expf(-fabsf(d)));
    float bm = r[SS + i];
    r[i] = sp;
    r[SS + i] = sp * bm;
}

// Sequential scan: g_t = clip(Ad_t @ g_{t-1} + dB_t * xs_t), s_t = dot(g_t, C_t)
// Per-step einsums in tf32 (operand rounding), fp32 accumulation.
__global__ void __launch_bounds__(256) scan_kernel(
    const float* __restrict__ ssm, const float* __restrict__ xsum,
    const float* __restrict__ A_log, float* __restrict__ sout)
{
    int b = blockIdx.x, tid = threadIdx.x;
    __shared__ float A_sh[SS];
    __shared__ __align__(16) float gbuf[2][SS];   // tf32-rounded state
    __shared__ float psum[2][8];
    if (tid < SS) {
        float al = A_log[tid];
        al = fminf(fmaxf(al, -5.f), 5.f);
        A_sh[tid] = -expf(al);
        gbuf[0][tid] = 0.f;
    }
    __syncthreads();
    int i = tid >> 2, sub = tid & 3;
    float Aj[16];
#pragma unroll
    for (int q = 0; q < 16; q++) Aj[q] = A_sh[sub * 16 + q];

    const float* row = ssm + (size_t)b * LL * LDSSM;
    const float* xsr = xsum + b * LL;
    float nd = row[i], ndb = row[SS + i], nC = row[2 * SS + i], nxs = xsr[0];

    for (int t = 0; t < LL; t++) {
        float d = nd, db = ndb, Cv = nC, xs = nxs;
        if (t + 1 < LL) {               // prefetch next step
            const float* r2 = row + (t + 1) * LDSSM;
            nd = r2[i]; ndb = r2[SS + i]; nC = r2[2 * SS + i]; nxs = xsr[t + 1];
        }
        int par = t & 1;
        const float4* g4 = (const float4*)(gbuf[par] + sub * 16);
        float acc = 0.f;
#pragma unroll
        for (int q4 = 0; q4 < 4; q4++) {
            float4 gv = g4[q4];   // already tf32-rounded at store
            acc += tf32r(expf(fminf(fmaxf(d * Aj[q4 * 4 + 0], -10.f), 0.f))) * gv.x;
            acc += tf32r(expf(fminf(fmaxf(d * Aj[q4 * 4 + 1], -10.f), 0.f))) * gv.y;
            acc += tf32r(expf(fminf(fmaxf(d * Aj[q4 * 4 + 2], -10.f), 0.f))) * gv.z;
            acc += tf32r(expf(fminf(fmaxf(d * Aj[q4 * 4 + 3], -10.f), 0.f))) * gv.w;
        }
        acc += __shfl_xor_sync(0xffffffffu, acc, 1);
        acc += __shfl_xor_sync(0xffffffffu, acc, 2);
        if (sub == 0) {
            float gn = acc + db * xs;            // fp32 add (ref order)
            gn = fminf(fmaxf(gn, -100.f), 100.f);
            float gr = tf32r(gn);                // einsum operand rounding
            gbuf[par ^ 1][i] = gr;
            float p = gr * tf32r(Cv);            // 'bse,bs->be' in tf32
            p += __shfl_xor_sync(0x11111111u, p, 4);
            p += __shfl_xor_sync(0x11111111u, p, 8);
            p += __shfl_xor_sync(0x11111111u, p, 16);
            if ((tid & 31) == 0) psum[par][tid >> 5] = p;
        }
        __syncthreads();
        if (tid == 0) {
            float t2 = 0.f;
#pragma unroll
            for (int w = 0; w < 8; w++) t2 += psum[par][w];
            sout[b * LL + t] = t2;
        }
    }
}

// y = s + D*x ; inner LN over E (two-pass variance); y *= silu(z). 256 thr/row.
__global__ void act_kernel(const float* __restrict__ xc, const float* __restrict__ s_in,
                           const float* __restrict__ xz, const float* __restrict__ D,
                           const float* __restrict__ ig, const float* __restrict__ ib,
                           float* __restrict__ y, int lastonly) {
    int m = lastonly ? (blockIdx.x * LL + (LL - 1)) : blockIdx.x;
    int e = threadIdx.x;
    float yv = s_in[m] + D[e] * xc[(size_t)m * EE + e];
    __shared__ float sh1[8], sh2[8];
    float s1 = yv;
#pragma unroll
    for (int o = 16; o; o >>= 1) s1 += __shfl_xor_sync(0xffffffffu, s1, o);
    if ((e & 31) == 0) sh1[e >> 5] = s1;
    __syncthreads();
    s1 = 0.f;
#pragma unroll
    for (int w = 0; w < 8; w++) s1 += sh1[w];
    float mean = s1 * (1.f / EE);
    float dcen = yv - mean;
    float s2 = dcen * dcen;
#pragma unroll
    for (int o = 16; o; o >>= 1) s2 += __shfl_xor_sync(0xffffffffu, s2, o);
    if ((e & 31) == 0) sh2[e >> 5] = s2;
    __syncthreads();
    s2 = 0.f;
#pragma unroll
    for (int w = 0; w < 8; w++) s2 += sh2[w];
    float var = s2 * (1.f / EE);
    float yn = dcen * rsqrtf(var + 1e-5f) * ig[e] + ib[e];
    float z = xz[(size_t)m * LDXZ + EE + e];
    y[(size_t)m * EE + e] = yn * (z / (1.f + expf(-z)));
}

// small projection for the last timestep rows only (block-2 z-half / C-cols)
__global__ void lastproj_kernel(const float* __restrict__ A, int lda,
                                const float* __restrict__ W, int ldw,
                                const float* __restrict__ bias,
                                float* __restrict__ C, int ldc,
                                int Kdim, int ncols, int coloff) {
    int b = blockIdx.x;
    int row = b * LL + (LL - 1);
    __shared__ float ush[EE];
    int tid = threadIdx.x;
    if (tid < Kdim) ush[tid] = tf32r(A[(size_t)row * lda + tid]);
    __syncthreads();
    for (int n = tid; n < ncols; n += blockDim.x) {
        float acc = 0.f;
        const float* wp = W + coloff + n;
#pragma unroll 4
        for (int k = 0; k < Kdim; k++) acc += ush[k] * tf32r(wp[(size_t)k * ldw]);
        C[(size_t)row * ldc + coloff + n] = acc + bias[coloff + n];
    }
}

// out-proj + residual + mask for last timestep rows (block 2)
__global__ void lastout_kernel(const float* __restrict__ y, const float* __restrict__ ow,
                               const float* __restrict__ ob, const int* __restrict__ seqs,
                               float* __restrict__ x) {
    int b = blockIdx.x, h = threadIdx.x;   // 128 threads
    int row = b * LL + (LL - 1);
    __shared__ float ysh[EE];
    ysh[h] = tf32r(y[(size_t)row * EE + h]);
    ysh[h + HH] = tf32r(y[(size_t)row * EE + h + HH]);
    __syncthreads();
    float acc = 0.f;
#pragma unroll 4
    for (int e = 0; e < EE; e++) acc += ysh[e] * tf32r(ow[e * HH + h]);
    float v = x[(size_t)row * HH + h] + (acc + ob[h]);
    x[(size_t)row * HH + h] = (seqs[row] != 0) ? v : 0.f;
}

// final LN (last timestep only, two-pass) + logits vs candidates (tf32 dot)
__global__ void final_kernel(const float* __restrict__ x, const int* __restrict__ idxs,
                             const float* __restrict__ item_emb,
                             const float* __restrict__ fg, const float* __restrict__ fb,
                             float* __restrict__ out) {
    int b = blockIdx.x, tid = threadIdx.x;   // 128 threads
    const float* xr = x + (size_t)(b * LL + LL - 1) * HH;
    float v = xr[tid];
    __shared__ float sh1[4], sh2[4];
    float s1 = v;
#pragma unroll
    for (int o = 16; o; o >>= 1) s1 += __shfl_xor_sync(0xffffffffu, s1, o);
    if ((tid & 31) == 0) sh1[tid >> 5] = s1;
    __syncthreads();
    float mean = (sh1[0] + sh1[1] + sh1[2] + sh1[3]) * (1.f / HH);
    float d = v - mean;
    float s2 = d * d;
#pragma unroll
    for (int o = 16; o; o >>= 1) s2 += __shfl_xor_sync(0xffffffffu, s2, o);
    if ((tid & 31) == 0) sh2[tid >> 5] = s2;
    __syncthreads();
    float var = (sh2[0] + sh2[1] + sh2[2] + sh2[3]) * (1.f / HH);
    __shared__ float xn[HH];
    xn[tid] = tf32r(d * rsqrtf(var + 1e-5f) * fg[tid] + fb[tid]);
    __syncthreads();
    int warp = tid >> 5, lane = tid & 31;
    for (int k = warp; k < KC; k += 4) {
        const float* er = item_emb + (size_t)idxs[b * KC + k] * HH;
        float p = xn[lane] * tf32r(er[lane]) + xn[lane + 32] * tf32r(er[lane + 32])
                + xn[lane + 64] * tf32r(er[lane + 64]) + xn[lane + 96] * tf32r(er[lane + 96]);
#pragma unroll
        for (int o = 16; o; o >>= 1) p += __shfl_xor_sync(0xffffffffu, p, o);
        if (lane == 0) out[b * KC + k] = p;
    }
}

// ---------------------------------------------------------------------------
extern "C" void kernel_launch(void* const* d_in, const int* in_sizes, int n_in,
                              void* d_out, int out_size) {
    (void)in_sizes; (void)n_in; (void)out_size;
    const int*   seqs     = (const int*)d_in[0];
    const int*   idxs     = (const int*)d_in[1];
    const float* item_emb = (const float*)d_in[2];
    const float* pos_emb  = (const float*)d_in[3];
    const float* blk_ln_g = (const float*)d_in[4];
    const float* blk_ln_b = (const float*)d_in[5];
    const float* in_w     = (const float*)d_in[6];
    const float* in_b     = (const float*)d_in[7];
    const float* conv_w   = (const float*)d_in[8];
    const float* conv_b   = (const float*)d_in[9];
    const float* xproj_w  = (const float*)d_in[10];
    const float* xproj_b  = (const float*)d_in[11];
    const float* A_log    = (const float*)d_in[12];
    const float* D_param  = (const float*)d_in[13];
    const float* out_w    = (const float*)d_in[14];
    const float* out_b    = (const float*)d_in[15];
    const float* inner_g  = (const float*)d_in[16];
    const float* inner_b  = (const float*)d_in[17];
    const float* final_g  = (const float*)d_in[18];
    const float* final_b  = (const float*)d_in[19];
    float* outp = (float*)d_out;

    float *px, *pu, *pxz, *pxc, *pssm, *py, *pxsum, *ps;
    cudaGetSymbolAddress((void**)&px, g_x);
    cudaGetSymbolAddress((void**)&pu, g_u);
    cudaGetSymbolAddress((void**)&pxz, g_xz);
    cudaGetSymbolAddress((void**)&pxc, g_xc);
    cudaGetSymbolAddress((void**)&pssm, g_ssm);
    cudaGetSymbolAddress((void**)&py, g_y);
    cudaGetSymbolAddress((void**)&pxsum, g_xsum);
    cudaGetSymbolAddress((void**)&ps, g_s);

    embed_kernel<<<MM, HH>>>(seqs, item_emb, pos_emb, px);

    for (int blk = 0; blk < NBLK; blk++) {
        const float* iw  = in_w    + (size_t)blk * HH * 2 * EE;
        const float* ibb = in_b    + blk * 2 * EE;
        const float* cw  = conv_w  + blk * EE * 3;
        const float* cb  = conv_b  + blk * EE;
        const float* xw  = xproj_w + (size_t)blk * EE * 3 * SS;
        const float* xb  = xproj_b + blk * 3 * SS;
        const float* al  = A_log   + blk * SS;
        const float* dp  = D_param + blk * EE;
        const float* ow  = out_w   + (size_t)blk * EE * HH;
        const float* ob  = out_b   + blk * HH;
        const float* ig  = inner_g + blk * EE;
        const float* ibn = inner_b + blk * EE;

        ln128_kernel<<<MM, HH>>>(px, pu, blk_ln_g + blk * HH, blk_ln_b + blk * HH);

        // in-projection: block 0 needs both x and z halves everywhere;
        // block 1 needs z only at the last timestep.
        int Nin = (blk == 0) ? (2 * EE) : EE;
        gemm_tc_kernel<<<dim3(Nin / 64, MM / 128), 256>>>(pu, HH, iw, 2 * EE, ibb,
                                                          pxz, 2 * EE, HH, 0, nullptr);
        if (blk == 1)
            lastproj_kernel<<<BB, 256>>>(pu, HH, iw, 2 * EE, ibb, pxz, 2 * EE,
                                         HH, EE, EE);

        conv_kernel<<<MM, EE>>>(pxz, cw, cb, pxc, pxsum);

        // x-projection: block 0 needs delta,B,C; block 1 needs C only at last t.
        int Nxp = (blk == 0) ? (3 * SS) : (2 * SS);
        gemm_tc_kernel<<<dim3(Nxp / 64, MM / 128), 256>>>(pxc, EE, xw, 3 * SS, xb,
                                                          pssm, LDSSM, EE, 0, nullptr);
        if (blk == 1)
            lastproj_kernel<<<BB, 256>>>(pxc, EE, xw, 3 * SS, xb, pssm, LDSSM,
                                         EE, SS, 2 * SS);

        ssmpost_kernel<<<MM, SS>>>(pssm);
        scan_kernel<<<BB, 256>>>(pssm, pxsum, al, ps);

        if (blk == 0) {
            act_kernel<<<MM, EE>>>(pxc, ps, pxz, dp, ig, ibn, py, 0);
            gemm_tc_kernel<<<dim3(HH / 64, MM / 128), 256>>>(py, EE, ow, HH, ob,
                                                             px, HH, EE, 1, seqs);
        } else {
            act_kernel<<<BB, EE>>>(pxc, ps, pxz, dp, ig, ibn, py, 1);
            lastout_kernel<<<BB, HH>>>(py, ow, ob, seqs, px);
        }
    }

    final_kernel<<<BB, HH>>>(px, idxs, item_emb, final_g, final_b, outp);
}

// round 11
// speedup vs baseline: 1.3017x; 1.1503x over previous
#include <cuda_runtime.h>
#include <cstdint>
#include <math.h>

#define BB 64
#define LL 200
#define HH 128
#define SS 64
#define EE 256
#define NBLK 2
#define MM (BB*LL)
#define KC 101
#define LDSSM 192
#define LDXZ (2*EE)

// TF32 round-to-nearest (matches tensor-core operand conversion; XLA default
// fp32 matmul/conv path on GPU = tf32 products, fp32 accumulation).
__device__ __forceinline__ float tf32r(float x) {
    float r;
    asm("cvt.rna.tf32.f32 %0, %1;" : "=f"(r) : "f"(x));
    return r;
}

__device__ __forceinline__ void mma_tf32(float c[4],
    uint32_t a0, uint32_t a1, uint32_t a2, uint32_t a3,
    uint32_t b0, uint32_t b1) {
    asm volatile(
        "mma.sync.aligned.m16n8k8.row.col.f32.tf32.tf32.f32 "
        "{%0,%1,%2,%3}, {%4,%5,%6,%7}, {%8,%9}, {%0,%1,%2,%3};\n"
        : "+f"(c[0]), "+f"(c[1]), "+f"(c[2]), "+f"(c[3])
        : "r"(a0), "r"(a1), "r"(a2), "r"(a3), "r"(b0), "r"(b1));
}

// Scratch (device globals — no allocation allowed)
__device__ __align__(16) float g_x[MM*HH];
__device__ __align__(16) float g_u[MM*HH];
__device__ __align__(16) float g_xz[MM*LDXZ];
__device__ __align__(16) float g_xc[MM*EE];
__device__ __align__(16) float g_ssm[MM*LDSSM];   // [delta_raw | B_raw | C]
__device__ __align__(16) float g_y[MM*EE];
__device__ __align__(16) float g_xsum[MM];
__device__ __align__(16) float g_s[MM];

// ---------------------------------------------------------------------------
// Fused embed + first-block LayerNorm. 128 threads per (b,l) row.
// Writes both x (residual stream) and u (normalized input to block 0).
__global__ void embed_ln_kernel(const int* __restrict__ seqs,
                                const float* __restrict__ item_emb,
                                const float* __restrict__ pos_emb,
                                const float* __restrict__ g, const float* __restrict__ b,
                                float* __restrict__ x, float* __restrict__ u) {
    int m = blockIdx.x, tid = threadIdx.x;
    int l = m % LL;
    int id = seqs[m];
    float v = item_emb[(size_t)id * HH + tid] + pos_emb[l * HH + tid];
    v = (id != 0) ? v : 0.f;
    x[(size_t)m * HH + tid] = v;
    __shared__ float sh1[4], sh2[4];
    float s1 = v;
#pragma unroll
    for (int o = 16; o; o >>= 1) s1 += __shfl_xor_sync(0xffffffffu, s1, o);
    if ((tid & 31) == 0) sh1[tid >> 5] = s1;
    __syncthreads();
    float mean = (sh1[0] + sh1[1] + sh1[2] + sh1[3]) * (1.f / HH);
    float d = v - mean;
    float s2 = d * d;
#pragma unroll
    for (int o = 16; o; o >>= 1) s2 += __shfl_xor_sync(0xffffffffu, s2, o);
    if ((tid & 31) == 0) sh2[tid >> 5] = s2;
    __syncthreads();
    float var = (sh2[0] + sh2[1] + sh2[2] + sh2[3]) * (1.f / HH);
    u[(size_t)m * HH + tid] = d * rsqrtf(var + 1e-5f) * g[tid] + b[tid];
}

// LayerNorm over H=128, one block per row (128 threads). Two-pass variance.
__global__ void ln128_kernel(const float* __restrict__ x, float* __restrict__ u,
                             const float* __restrict__ g, const float* __restrict__ b) {
    int m = blockIdx.x, tid = threadIdx.x;
    float v = x[(size_t)m * HH + tid];
    __shared__ float sh1[4], sh2[4];
    float s1 = v;
#pragma unroll
    for (int o = 16; o; o >>= 1) s1 += __shfl_xor_sync(0xffffffffu, s1, o);
    if ((tid & 31) == 0) sh1[tid >> 5] = s1;
    __syncthreads();
    float mean = (sh1[0] + sh1[1] + sh1[2] + sh1[3]) * (1.f / HH);
    float d = v - mean;
    float s2 = d * d;
#pragma unroll
    for (int o = 16; o; o >>= 1) s2 += __shfl_xor_sync(0xffffffffu, s2, o);
    if ((tid & 31) == 0) sh2[tid >> 5] = s2;
    __syncthreads();
    float var = (sh2[0] + sh2[1] + sh2[2] + sh2[3]) * (1.f / HH);
    u[(size_t)m * HH + tid] = d * rsqrtf(var + 1e-5f) * g[tid] + b[tid];
}

// ---------------------------------------------------------------------------
// TF32 tensor-core GEMM: C[M,N] = A[M,K] @ W[K,N] + bias.
// BM=128, BN=64, BK=16; 8 warps (4m x 2n), warp tile 32x32 via m16n8k8 tf32.
// epi==1: C = (resid + C + bias) * mask (residual in C).
#define APAD 20
#define BPAD 72
__global__ void __launch_bounds__(256) gemm_tc_kernel(
    const float* __restrict__ A, int lda,
    const float* __restrict__ W, int ldw,
    const float* __restrict__ bias,
    float* __restrict__ C, int ldc,
    int Kdim, int epi, const int* __restrict__ seqs)
{
    __shared__ __align__(16) float As[2][128 * APAD];
    __shared__ __align__(16) float Ws[2][16 * BPAD];
    int tid = threadIdx.x;
    int m0 = blockIdx.y << 7, n0 = blockIdx.x << 6;
    int lane = tid & 31, wid = tid >> 5;
    int wm = (wid & 3) << 5;       // warp m offset: 0,32,64,96
    int wn = (wid >> 2) << 5;      // warp n offset: 0,32
    int g = lane >> 2, cq = lane & 3;

    int a_r = tid >> 2, a_q = tid & 3;
    int b_k = tid >> 4, b_q = tid & 15;
    const float* ApBase = A + (size_t)(m0 + a_r) * lda + (a_q << 2);
    const float* WpBase = W + (size_t)b_k * ldw + n0 + (b_q << 2);

    float acc[2][4][4];
#pragma unroll
    for (int i = 0; i < 2; i++)
#pragma unroll
        for (int j = 0; j < 4; j++)
#pragma unroll
            for (int q = 0; q < 4; q++) acc[i][j][q] = 0.f;

    float4 av0 = *(const float4*)(ApBase);
    float4 av1 = *(const float4*)(ApBase + (size_t)64 * lda);
    float4 bv  = *(const float4*)(WpBase);
    {
        float4 t0, t1, tb;
        t0.x = tf32r(av0.x); t0.y = tf32r(av0.y); t0.z = tf32r(av0.z); t0.w = tf32r(av0.w);
        t1.x = tf32r(av1.x); t1.y = tf32r(av1.y); t1.z = tf32r(av1.z); t1.w = tf32r(av1.w);
        tb.x = tf32r(bv.x);  tb.y = tf32r(bv.y);  tb.z = tf32r(bv.z);  tb.w = tf32r(bv.w);
        *(float4*)&As[0][a_r * APAD + (a_q << 2)] = t0;
        *(float4*)&As[0][(a_r + 64) * APAD + (a_q << 2)] = t1;
        *(float4*)&Ws[0][b_k * BPAD + (b_q << 2)] = tb;
    }
    __syncthreads();

    int nk = Kdim >> 4;
    for (int kt = 0; kt < nk; kt++) {
        int cur = kt & 1;
        if (kt + 1 < nk) {
            av0 = *(const float4*)(ApBase + ((kt + 1) << 4));
            av1 = *(const float4*)(ApBase + (size_t)64 * lda + ((kt + 1) << 4));
            bv  = *(const float4*)(WpBase + (size_t)((kt + 1) << 4) * ldw);
        }
#pragma unroll
        for (int ks = 0; ks < 2; ks++) {
            int kk = ks << 3;
            uint32_t bf[4][2];
#pragma unroll
            for (int j = 0; j < 4; j++) {
                bf[j][0] = __float_as_uint(Ws[cur][(kk + cq) * BPAD + wn + (j << 3) + g]);
                bf[j][1] = __float_as_uint(Ws[cur][(kk + cq + 4) * BPAD + wn + (j << 3) + g]);
            }
#pragma unroll
            for (int i = 0; i < 2; i++) {
                const float* ab = &As[cur][(wm + (i << 4)) * APAD + kk + cq];
                uint32_t a0 = __float_as_uint(ab[g * APAD]);
                uint32_t a1 = __float_as_uint(ab[(g + 8) * APAD]);
                uint32_t a2 = __float_as_uint(ab[g * APAD + 4]);
                uint32_t a3 = __float_as_uint(ab[(g + 8) * APAD + 4]);
#pragma unroll
                for (int j = 0; j < 4; j++)
                    mma_tf32(acc[i][j], a0, a1, a2, a3, bf[j][0], bf[j][1]);
            }
        }
        if (kt + 1 < nk) {
            int nxt = cur ^ 1;
            float4 t0, t1, tb;
            t0.x = tf32r(av0.x); t0.y = tf32r(av0.y); t0.z = tf32r(av0.z); t0.w = tf32r(av0.w);
            t1.x = tf32r(av1.x); t1.y = tf32r(av1.y); t1.z = tf32r(av1.z); t1.w = tf32r(av1.w);
            tb.x = tf32r(bv.x);  tb.y = tf32r(bv.y);  tb.z = tf32r(bv.z);  tb.w = tf32r(bv.w);
            *(float4*)&As[nxt][a_r * APAD + (a_q << 2)] = t0;
            *(float4*)&As[nxt][(a_r + 64) * APAD + (a_q << 2)] = t1;
            *(float4*)&Ws[nxt][b_k * BPAD + (b_q << 2)] = tb;
        }
        __syncthreads();
    }

#pragma unroll
    for (int i = 0; i < 2; i++) {
        int r0 = m0 + wm + (i << 4) + g;
        int r1 = r0 + 8;
        float msk0 = 1.f, msk1 = 1.f;
        if (epi == 1) {
            msk0 = (seqs[r0] != 0) ? 1.f : 0.f;
            msk1 = (seqs[r1] != 0) ? 1.f : 0.f;
        }
#pragma unroll
        for (int j = 0; j < 4; j++) {
            int col = n0 + wn + (j << 3) + (cq << 1);
            float b0 = bias[col], b1 = bias[col + 1];
            size_t o0 = (size_t)r0 * ldc + col;
            size_t o1 = (size_t)r1 * ldc + col;
            float v00 = acc[i][j][0] + b0, v01 = acc[i][j][1] + b1;
            float v10 = acc[i][j][2] + b0, v11 = acc[i][j][3] + b1;
            if (epi == 1) {
                v00 = (C[o0] + v00) * msk0; v01 = (C[o0 + 1] + v01) * msk0;
                v10 = (C[o1] + v10) * msk1; v11 = (C[o1 + 1] + v11) * msk1;
            }
            C[o0] = v00; C[o0 + 1] = v01;
            C[o1] = v10; C[o1 + 1] = v11;
        }
    }
}

// depthwise conv k=3 pad (1,1) + silu + row-sum. TF32 products.
__global__ void conv_kernel(const float* __restrict__ xz,
                            const float* __restrict__ cw, const float* __restrict__ cb,
                            float* __restrict__ xc, float* __restrict__ xsum) {
    int m = blockIdx.x, e = threadIdx.x;
    int l = m % LL;
    const float* xr = xz + (size_t)m * LDXZ;
    float w0 = tf32r(cw[e * 3]), w1 = tf32r(cw[e * 3 + 1]), w2 = tf32r(cw[e * 3 + 2]);
    float acc = tf32r(xr[e]) * w1;
    if (l > 0) acc += tf32r(xr[e - LDXZ]) * w0;
    if (l < LL - 1) acc += tf32r(xr[e + LDXZ]) * w2;
    acc += cb[e];
    float sv = acc / (1.f + __expf(-acc));   // silu (fast exp: error << tf32 ulp)
    xc[(size_t)m * EE + e] = sv;
    float s = sv;
#pragma unroll
    for (int o = 16; o; o >>= 1) s += __shfl_xor_sync(0xffffffffu, s, o);
    __shared__ float sh[8];
    if ((e & 31) == 0) sh[e >> 5] = s;
    __syncthreads();
    if (e == 0) {
        float t = 0.f;
#pragma unroll
        for (int w = 0; w < 8; w++) t += sh[w];
        xsum[m] = t;
    }
}

// Sequential scan with fused softplus/dB: reads RAW delta & B from ssm.
// g_t = clip(Ad_t @ g_{t-1} + dB_t*xs_t); s_t = dot(g_t, C_t) (tf32 operands).
// lastonly: emit s only at t = LL-1 (block 1 — only the last timestep is used).
__global__ void __launch_bounds__(256) scan_kernel(
    const float* __restrict__ ssm, const float* __restrict__ xsum,
    const float* __restrict__ A_log, float* __restrict__ sout, int lastonly)
{
    int b = blockIdx.x, tid = threadIdx.x;
    __shared__ float A_sh[SS];
    __shared__ __align__(16) float gbuf[2][SS];   // tf32-rounded state
    __shared__ float psum[8];
    if (tid < SS) {
        float al = A_log[tid];
        al = fminf(fmaxf(al, -5.f), 5.f);
        A_sh[tid] = -expf(al);
        gbuf[0][tid] = 0.f;
    }
    __syncthreads();
    int i = tid >> 2, sub = tid & 3;
    float Aj[16];
#pragma unroll
    for (int q = 0; q < 16; q++) Aj[q] = A_sh[sub * 16 + q];

    const float* row = ssm + (size_t)b * LL * LDSSM;
    const float* xsr = xsum + b * LL;
    float nd = row[i], nbm = row[SS + i], nC = row[2 * SS + i], nxs = xsr[0];

    for (int t = 0; t < LL; t++) {
        float draw = nd, bm = nbm, Cv = nC, xs = nxs;
        if (t + 1 < LL) {               // prefetch next step
            const float* r2 = row + (t + 1) * LDSSM;
            nd = r2[i]; nbm = r2[SS + i]; nC = r2[2 * SS + i]; nxs = xsr[t + 1];
        }
        // softplus (fused; __expf error << tf32 quantum downstream)
        float d = fmaxf(draw, 0.f) + log1pf(__expf(-fabsf(draw)));
        float db = d * bm;
        int par = t & 1;
        const float4* g4 = (const float4*)(gbuf[par] + sub * 16);
        float acc = 0.f;
#pragma unroll
        for (int q4 = 0; q4 < 4; q4++) {
            float4 gv = g4[q4];   // already tf32-rounded at store
            acc += tf32r(__expf(fminf(fmaxf(d * Aj[q4 * 4 + 0], -10.f), 0.f))) * gv.x;
            acc += tf32r(__expf(fminf(fmaxf(d * Aj[q4 * 4 + 1], -10.f), 0.f))) * gv.y;
            acc += tf32r(__expf(fminf(fmaxf(d * Aj[q4 * 4 + 2], -10.f), 0.f))) * gv.z;
            acc += tf32r(__expf(fminf(fmaxf(d * Aj[q4 * 4 + 3], -10.f), 0.f))) * gv.w;
        }
        acc += __shfl_xor_sync(0xffffffffu, acc, 1);
        acc += __shfl_xor_sync(0xffffffffu, acc, 2);
        int emit = (!lastonly) || (t == LL - 1);
        if (sub == 0) {
            float gn = acc + db * xs;            // fp32 add (ref order)
            gn = fminf(fmaxf(gn, -100.f), 100.f);
            float gr = tf32r(gn);                // einsum operand rounding
            gbuf[par ^ 1][i] = gr;
            if (emit) {
                float p = gr * tf32r(Cv);        // 'bse,bs->be' in tf32
                p += __shfl_xor_sync(0x11111111u, p, 4);
                p += __shfl_xor_sync(0x11111111u, p, 8);
                p += __shfl_xor_sync(0x11111111u, p, 16);
                if ((tid & 31) == 0) psum[tid >> 5] = p;
            }
        }
        __syncthreads();
        if (emit && tid == 0) {
            float t2 = 0.f;
#pragma unroll
            for (int w = 0; w < 8; w++) t2 += psum[w];
            sout[b * LL + t] = t2;
        }
    }
}

// y = s + D*x ; inner LN over E (two-pass variance); y *= silu(z). 256 thr/row.
__global__ void act_kernel(const float* __restrict__ xc, const float* __restrict__ s_in,
                           const float* __restrict__ xz, const float* __restrict__ D,
                           const float* __restrict__ ig, const float* __restrict__ ib,
                           float* __restrict__ y, int lastonly) {
    int m = lastonly ? (blockIdx.x * LL + (LL - 1)) : blockIdx.x;
    int e = threadIdx.x;
    float yv = s_in[m] + D[e] * xc[(size_t)m * EE + e];
    __shared__ float sh1[8], sh2[8];
    float s1 = yv;
#pragma unroll
    for (int o = 16; o; o >>= 1) s1 += __shfl_xor_sync(0xffffffffu, s1, o);
    if ((e & 31) == 0) sh1[e >> 5] = s1;
    __syncthreads();
    s1 = 0.f;
#pragma unroll
    for (int w = 0; w < 8; w++) s1 += sh1[w];
    float mean = s1 * (1.f / EE);
    float dcen = yv - mean;
    float s2 = dcen * dcen;
#pragma unroll
    for (int o = 16; o; o >>= 1) s2 += __shfl_xor_sync(0xffffffffu, s2, o);
    if ((e & 31) == 0) sh2[e >> 5] = s2;
    __syncthreads();
    s2 = 0.f;
#pragma unroll
    for (int w = 0; w < 8; w++) s2 += sh2[w];
    float var = s2 * (1.f / EE);
    float yn = dcen * rsqrtf(var + 1e-5f) * ig[e] + ib[e];
    float z = xz[(size_t)m * LDXZ + EE + e];
    y[(size_t)m * EE + e] = yn * (z / (1.f + __expf(-z)));
}

// small projection for the last timestep rows only (block-2 z-half / C-cols)
__global__ void lastproj_kernel(const float* __restrict__ A, int lda,
                                const float* __restrict__ W, int ldw,
                                const float* __restrict__ bias,
                                float* __restrict__ C, int ldc,
                                int Kdim, int ncols, int coloff) {
    int b = blockIdx.x;
    int row = b * LL + (LL - 1);
    __shared__ float ush[EE];
    int tid = threadIdx.x;
    if (tid < Kdim) ush[tid] = tf32r(A[(size_t)row * lda + tid]);
    __syncthreads();
    for (int n = tid; n < ncols; n += blockDim.x) {
        float acc = 0.f;
        const float* wp = W + coloff + n;
#pragma unroll 4
        for (int k = 0; k < Kdim; k++) acc += ush[k] * tf32r(wp[(size_t)k * ldw]);
        C[(size_t)row * ldc + coloff + n] = acc + bias[coloff + n];
    }
}

// out-proj + residual + mask for last timestep rows (block 2)
__global__ void lastout_kernel(const float* __restrict__ y, const float* __restrict__ ow,
                               const float* __restrict__ ob, const int* __restrict__ seqs,
                               float* __restrict__ x) {
    int b = blockIdx.x, h = threadIdx.x;   // 128 threads
    int row = b * LL + (LL - 1);
    __shared__ float ysh[EE];
    ysh[h] = tf32r(y[(size_t)row * EE + h]);
    ysh[h + HH] = tf32r(y[(size_t)row * EE + h + HH]);
    __syncthreads();
    float acc = 0.f;
#pragma unroll 4
    for (int e = 0; e < EE; e++) acc += ysh[e] * tf32r(ow[e * HH + h]);
    float v = x[(size_t)row * HH + h] + (acc + ob[h]);
    x[(size_t)row * HH + h] = (seqs[row] != 0) ? v : 0.f;
}

// final LN (last timestep only, two-pass) + logits vs candidates (tf32 dot)
__global__ void final_kernel(const float* __restrict__ x, const int* __restrict__ idxs,
                             const float* __restrict__ item_emb,
                             const float* __restrict__ fg, const float* __restrict__ fb,
                             float* __restrict__ out) {
    int b = blockIdx.x, tid = threadIdx.x;   // 128 threads
    const float* xr = x + (size_t)(b * LL + LL - 1) * HH;
    float v = xr[tid];
    __shared__ float sh1[4], sh2[4];
    float s1 = v;
#pragma unroll
    for (int o = 16; o; o >>= 1) s1 += __shfl_xor_sync(0xffffffffu, s1, o);
    if ((tid & 31) == 0) sh1[tid >> 5] = s1;
    __syncthreads();
    float mean = (sh1[0] + sh1[1] + sh1[2] + sh1[3]) * (1.f / HH);
    float d = v - mean;
    float s2 = d * d;
#pragma unroll
    for (int o = 16; o; o >>= 1) s2 += __shfl_xor_sync(0xffffffffu, s2, o);
    if ((tid & 31) == 0) sh2[tid >> 5] = s2;
    __syncthreads();
    float var = (sh2[0] + sh2[1] + sh2[2] + sh2[3]) * (1.f / HH);
    __shared__ float xn[HH];
    xn[tid] = tf32r(d * rsqrtf(var + 1e-5f) * fg[tid] + fb[tid]);
    __syncthreads();
    int warp = tid >> 5, lane = tid & 31;
    for (int k = warp; k < KC; k += 4) {
        const float* er = item_emb + (size_t)idxs[b * KC + k] * HH;
        float p = xn[lane] * tf32r(er[lane]) + xn[lane + 32] * tf32r(er[lane + 32])
                + xn[lane + 64] * tf32r(er[lane + 64]) + xn[lane + 96] * tf32r(er[lane + 96]);
#pragma unroll
        for (int o = 16; o; o >>= 1) p += __shfl_xor_sync(0xffffffffu, p, o);
        if (lane == 0) out[b * KC + k] = p;
    }
}

// ---------------------------------------------------------------------------
extern "C" void kernel_launch(void* const* d_in, const int* in_sizes, int n_in,
                              void* d_out, int out_size) {
    (void)in_sizes; (void)n_in; (void)out_size;
    const int*   seqs     = (const int*)d_in[0];
    const int*   idxs     = (const int*)d_in[1];
    const float* item_emb = (const float*)d_in[2];
    const float* pos_emb  = (const float*)d_in[3];
    const float* blk_ln_g = (const float*)d_in[4];
    const float* blk_ln_b = (const float*)d_in[5];
    const float* in_w     = (const float*)d_in[6];
    const float* in_b     = (const float*)d_in[7];
    const float* conv_w   = (const float*)d_in[8];
    const float* conv_b   = (const float*)d_in[9];
    const float* xproj_w  = (const float*)d_in[10];
    const float* xproj_b  = (const float*)d_in[11];
    const float* A_log    = (const float*)d_in[12];
    const float* D_param  = (const float*)d_in[13];
    const float* out_w    = (const float*)d_in[14];
    const float* out_b    = (const float*)d_in[15];
    const float* inner_g  = (const float*)d_in[16];
    const float* inner_b  = (const float*)d_in[17];
    const float* final_g  = (const float*)d_in[18];
    const float* final_b  = (const float*)d_in[19];
    float* outp = (float*)d_out;

    float *px, *pu, *pxz, *pxc, *pssm, *py, *pxsum, *ps;
    cudaGetSymbolAddress((void**)&px, g_x);
    cudaGetSymbolAddress((void**)&pu, g_u);
    cudaGetSymbolAddress((void**)&pxz, g_xz);
    cudaGetSymbolAddress((void**)&pxc, g_xc);
    cudaGetSymbolAddress((void**)&pssm, g_ssm);
    cudaGetSymbolAddress((void**)&py, g_y);
    cudaGetSymbolAddress((void**)&pxsum, g_xsum);
    cudaGetSymbolAddress((void**)&ps, g_s);

    for (int blk = 0; blk < NBLK; blk++) {
        const float* iw  = in_w    + (size_t)blk * HH * 2 * EE;
        const float* ibb = in_b    + blk * 2 * EE;
        const float* cw  = conv_w  + blk * EE * 3;
        const float* cb  = conv_b  + blk * EE;
        const float* xw  = xproj_w + (size_t)blk * EE * 3 * SS;
        const float* xb  = xproj_b + blk * 3 * SS;
        const float* al  = A_log   + blk * SS;
        const float* dp  = D_param + blk * EE;
        const float* ow  = out_w   + (size_t)blk * EE * HH;
        const float* ob  = out_b   + blk * HH;
        const float* ig  = inner_g + blk * EE;
        const float* ibn = inner_b + blk * EE;

        if (blk == 0)
            embed_ln_kernel<<<MM, HH>>>(seqs, item_emb, pos_emb,
                                        blk_ln_g, blk_ln_b, px, pu);
        else
            ln128_kernel<<<MM, HH>>>(px, pu, blk_ln_g + blk * HH, blk_ln_b + blk * HH);

        // in-projection: block 0 needs both x and z halves everywhere;
        // block 1 needs z only at the last timestep.
        int Nin = (blk == 0) ? (2 * EE) : EE;
        gemm_tc_kernel<<<dim3(Nin / 64, MM / 128), 256>>>(pu, HH, iw, 2 * EE, ibb,
                                                          pxz, 2 * EE, HH, 0, nullptr);
        if (blk == 1)
            lastproj_kernel<<<BB, 256>>>(pu, HH, iw, 2 * EE, ibb, pxz, 2 * EE,
                                         HH, EE, EE);

        conv_kernel<<<MM, EE>>>(pxz, cw, cb, pxc, pxsum);

        // x-projection: block 0 needs delta,B,C; block 1 needs C only at last t.
        int Nxp = (blk == 0) ? (3 * SS) : (2 * SS);
        gemm_tc_kernel<<<dim3(Nxp / 64, MM / 128), 256>>>(pxc, EE, xw, 3 * SS, xb,
                                                          pssm, LDSSM, EE, 0, nullptr);
        if (blk == 1)
            lastproj_kernel<<<BB, 256>>>(pxc, EE, xw, 3 * SS, xb, pssm, LDSSM,
                                         EE, SS, 2 * SS);

        scan_kernel<<<BB, 256>>>(pssm, pxsum, al, ps, (blk == 1) ? 1 : 0);

        if (blk == 0) {
            act_kernel<<<MM, EE>>>(pxc, ps, pxz, dp, ig, ibn, py, 0);
            gemm_tc_kernel<<<dim3(HH / 64, MM / 128), 256>>>(py, EE, ow, HH, ob,
                                                             px, HH, EE, 1, seqs);
        } else {
            act_kernel<<<BB, EE>>>(pxc, ps, pxz, dp, ig, ibn, py, 1);
            lastout_kernel<<<BB, HH>>>(py, ow, ob, seqs, px);
        }
    }

    final_kernel<<<BB, HH>>>(px, idxs, item_emb, final_g, final_b, outp);
}

// round 12
// speedup vs baseline: 1.3715x; 1.0537x over previous
#include <cuda_runtime.h>
#include <cstdint>
#include <math.h>

#define BB 64
#define LL 200
#define HH 128
#define SS 64
#define EE 256
#define NBLK 2
#define MM (BB*LL)
#define KC 101
#define LDSSM 192
#define LDXZ (2*EE)

// TF32 round-to-nearest (matches tensor-core operand conversion; XLA default
// fp32 matmul/conv path on GPU = tf32 products, fp32 accumulation).
__device__ __forceinline__ float tf32r(float x) {
    float r;
    asm("cvt.rna.tf32.f32 %0, %1;" : "=f"(r) : "f"(x));
    return r;
}

__device__ __forceinline__ void mma_tf32(float c[4],
    uint32_t a0, uint32_t a1, uint32_t a2, uint32_t a3,
    uint32_t b0, uint32_t b1) {
    asm volatile(
        "mma.sync.aligned.m16n8k8.row.col.f32.tf32.tf32.f32 "
        "{%0,%1,%2,%3}, {%4,%5,%6,%7}, {%8,%9}, {%0,%1,%2,%3};\n"
        : "+f"(c[0]), "+f"(c[1]), "+f"(c[2]), "+f"(c[3])
        : "r"(a0), "r"(a1), "r"(a2), "r"(a3), "r"(b0), "r"(b1));
}

__device__ __forceinline__ float wredsum(float v) {
#pragma unroll
    for (int o = 16; o; o >>= 1) v += __shfl_xor_sync(0xffffffffu, v, o);
    return v;
}

// Scratch (device globals — no allocation allowed)
__device__ __align__(16) float g_x[MM*HH];
__device__ __align__(16) float g_u[MM*HH];
__device__ __align__(16) float g_xz[MM*LDXZ];
__device__ __align__(16) float g_xc[MM*EE];
__device__ __align__(16) float g_ssm[MM*LDSSM];   // [delta_raw | B_raw | C]
__device__ __align__(16) float g_y[MM*EE];
__device__ __align__(16) float g_xsum[MM];
__device__ __align__(16) float g_s[MM];

// ---------------------------------------------------------------------------
// Fused embed + first-block LayerNorm. Warp per row, float4, 8 rows/CTA.
__global__ void __launch_bounds__(256) embed_ln_kernel(
    const int* __restrict__ seqs,
    const float* __restrict__ item_emb, const float* __restrict__ pos_emb,
    const float* __restrict__ g, const float* __restrict__ b,
    float* __restrict__ x, float* __restrict__ u) {
    int warp = threadIdx.x >> 5, lane = threadIdx.x & 31;
    int m = blockIdx.x * 8 + warp;
    int l = m % LL;
    int id = seqs[m];
    int e = lane << 2;
    float4 ie = *(const float4*)(item_emb + (size_t)id * HH + e);
    float4 pe = *(const float4*)(pos_emb + l * HH + e);
    float msk = (id != 0) ? 1.f : 0.f;
    float4 v;
    v.x = (ie.x + pe.x) * msk; v.y = (ie.y + pe.y) * msk;
    v.z = (ie.z + pe.z) * msk; v.w = (ie.w + pe.w) * msk;
    *(float4*)(x + (size_t)m * HH + e) = v;
    float mean = wredsum(v.x + v.y + v.z + v.w) * (1.f / HH);
    float4 d; d.x = v.x - mean; d.y = v.y - mean; d.z = v.z - mean; d.w = v.w - mean;
    float var = wredsum(d.x * d.x + d.y * d.y + d.z * d.z + d.w * d.w) * (1.f / HH);
    float inv = rsqrtf(var + 1e-5f);
    float4 gg = *(const float4*)(g + e);
    float4 bb = *(const float4*)(b + e);
    float4 o;
    o.x = d.x * inv * gg.x + bb.x; o.y = d.y * inv * gg.y + bb.y;
    o.z = d.z * inv * gg.z + bb.z; o.w = d.w * inv * gg.w + bb.w;
    *(float4*)(u + (size_t)m * HH + e) = o;
}

// LayerNorm over H=128. Warp per row, float4, 8 rows/CTA. Two-pass variance.
__global__ void __launch_bounds__(256) ln128_kernel(
    const float* __restrict__ x, float* __restrict__ u,
    const float* __restrict__ g, const float* __restrict__ b) {
    int warp = threadIdx.x >> 5, lane = threadIdx.x & 31;
    int m = blockIdx.x * 8 + warp;
    int e = lane << 2;
    float4 v = *(const float4*)(x + (size_t)m * HH + e);
    float mean = wredsum(v.x + v.y + v.z + v.w) * (1.f / HH);
    float4 d; d.x = v.x - mean; d.y = v.y - mean; d.z = v.z - mean; d.w = v.w - mean;
    float var = wredsum(d.x * d.x + d.y * d.y + d.z * d.z + d.w * d.w) * (1.f / HH);
    float inv = rsqrtf(var + 1e-5f);
    float4 gg = *(const float4*)(g + e);
    float4 bb = *(const float4*)(b + e);
    float4 o;
    o.x = d.x * inv * gg.x + bb.x; o.y = d.y * inv * gg.y + bb.y;
    o.z = d.z * inv * gg.z + bb.z; o.w = d.w * inv * gg.w + bb.w;
    *(float4*)(u + (size_t)m * HH + e) = o;
}

// ---------------------------------------------------------------------------
// TF32 tensor-core GEMM: C[M,N] = A[M,K] @ W[K,N] + bias.
// BM=128, BN=64, BK=16; 8 warps (4m x 2n), warp tile 32x32 via m16n8k8 tf32.
// epi==1: C = (resid + C + bias) * mask (residual in C).
#define APAD 20
#define BPAD 72
__global__ void __launch_bounds__(256) gemm_tc_kernel(
    const float* __restrict__ A, int lda,
    const float* __restrict__ W, int ldw,
    const float* __restrict__ bias,
    float* __restrict__ C, int ldc,
    int Kdim, int epi, const int* __restrict__ seqs)
{
    __shared__ __align__(16) float As[2][128 * APAD];
    __shared__ __align__(16) float Ws[2][16 * BPAD];
    int tid = threadIdx.x;
    int m0 = blockIdx.y << 7, n0 = blockIdx.x << 6;
    int lane = tid & 31, wid = tid >> 5;
    int wm = (wid & 3) << 5;
    int wn = (wid >> 2) << 5;
    int g = lane >> 2, cq = lane & 3;

    int a_r = tid >> 2, a_q = tid & 3;
    int b_k = tid >> 4, b_q = tid & 15;
    const float* ApBase = A + (size_t)(m0 + a_r) * lda + (a_q << 2);
    const float* WpBase = W + (size_t)b_k * ldw + n0 + (b_q << 2);

    float acc[2][4][4];
#pragma unroll
    for (int i = 0; i < 2; i++)
#pragma unroll
        for (int j = 0; j < 4; j++)
#pragma unroll
            for (int q = 0; q < 4; q++) acc[i][j][q] = 0.f;

    float4 av0 = *(const float4*)(ApBase);
    float4 av1 = *(const float4*)(ApBase + (size_t)64 * lda);
    float4 bv  = *(const float4*)(WpBase);
    {
        float4 t0, t1, tb;
        t0.x = tf32r(av0.x); t0.y = tf32r(av0.y); t0.z = tf32r(av0.z); t0.w = tf32r(av0.w);
        t1.x = tf32r(av1.x); t1.y = tf32r(av1.y); t1.z = tf32r(av1.z); t1.w = tf32r(av1.w);
        tb.x = tf32r(bv.x);  tb.y = tf32r(bv.y);  tb.z = tf32r(bv.z);  tb.w = tf32r(bv.w);
        *(float4*)&As[0][a_r * APAD + (a_q << 2)] = t0;
        *(float4*)&As[0][(a_r + 64) * APAD + (a_q << 2)] = t1;
        *(float4*)&Ws[0][b_k * BPAD + (b_q << 2)] = tb;
    }
    __syncthreads();

    int nk = Kdim >> 4;
    for (int kt = 0; kt < nk; kt++) {
        int cur = kt & 1;
        if (kt + 1 < nk) {
            av0 = *(const float4*)(ApBase + ((kt + 1) << 4));
            av1 = *(const float4*)(ApBase + (size_t)64 * lda + ((kt + 1) << 4));
            bv  = *(const float4*)(WpBase + (size_t)((kt + 1) << 4) * ldw);
        }
#pragma unroll
        for (int ks = 0; ks < 2; ks++) {
            int kk = ks << 3;
            uint32_t bf[4][2];
#pragma unroll
            for (int j = 0; j < 4; j++) {
                bf[j][0] = __float_as_uint(Ws[cur][(kk + cq) * BPAD + wn + (j << 3) + g]);
                bf[j][1] = __float_as_uint(Ws[cur][(kk + cq + 4) * BPAD + wn + (j << 3) + g]);
            }
#pragma unroll
            for (int i = 0; i < 2; i++) {
                const float* ab = &As[cur][(wm + (i << 4)) * APAD + kk + cq];
                uint32_t a0 = __float_as_uint(ab[g * APAD]);
                uint32_t a1 = __float_as_uint(ab[(g + 8) * APAD]);
                uint32_t a2 = __float_as_uint(ab[g * APAD + 4]);
                uint32_t a3 = __float_as_uint(ab[(g + 8) * APAD + 4]);
#pragma unroll
                for (int j = 0; j < 4; j++)
                    mma_tf32(acc[i][j], a0, a1, a2, a3, bf[j][0], bf[j][1]);
            }
        }
        if (kt + 1 < nk) {
            int nxt = cur ^ 1;
            float4 t0, t1, tb;
            t0.x = tf32r(av0.x); t0.y = tf32r(av0.y); t0.z = tf32r(av0.z); t0.w = tf32r(av0.w);
            t1.x = tf32r(av1.x); t1.y = tf32r(av1.y); t1.z = tf32r(av1.z); t1.w = tf32r(av1.w);
            tb.x = tf32r(bv.x);  tb.y = tf32r(bv.y);  tb.z = tf32r(bv.z);  tb.w = tf32r(bv.w);
            *(float4*)&As[nxt][a_r * APAD + (a_q << 2)] = t0;
            *(float4*)&As[nxt][(a_r + 64) * APAD + (a_q << 2)] = t1;
            *(float4*)&Ws[nxt][b_k * BPAD + (b_q << 2)] = tb;
        }
        __syncthreads();
    }

#pragma unroll
    for (int i = 0; i < 2; i++) {
        int r0 = m0 + wm + (i << 4) + g;
        int r1 = r0 + 8;
        float msk0 = 1.f, msk1 = 1.f;
        if (epi == 1) {
            msk0 = (seqs[r0] != 0) ? 1.f : 0.f;
            msk1 = (seqs[r1] != 0) ? 1.f : 0.f;
        }
#pragma unroll
        for (int j = 0; j < 4; j++) {
            int col = n0 + wn + (j << 3) + (cq << 1);
            float b0 = bias[col], b1 = bias[col + 1];
            size_t o0 = (size_t)r0 * ldc + col;
            size_t o1 = (size_t)r1 * ldc + col;
            float v00 = acc[i][j][0] + b0, v01 = acc[i][j][1] + b1;
            float v10 = acc[i][j][2] + b0, v11 = acc[i][j][3] + b1;
            if (epi == 1) {
                v00 = (C[o0] + v00) * msk0; v01 = (C[o0 + 1] + v01) * msk0;
                v10 = (C[o1] + v10) * msk1; v11 = (C[o1 + 1] + v11) * msk1;
            }
            C[o0] = v00; C[o0 + 1] = v01;
            C[o1] = v10; C[o1 + 1] = v11;
        }
    }
}

// depthwise conv k=3 pad (1,1) + silu + row-sum. Warp per row, 8 rows/CTA.
__global__ void __launch_bounds__(256) conv_kernel(
    const float* __restrict__ xz,
    const float* __restrict__ cw, const float* __restrict__ cb,
    float* __restrict__ xc, float* __restrict__ xsum) {
    int warp = threadIdx.x >> 5, lane = threadIdx.x & 31;
    int m = blockIdx.x * 8 + warp;
    int l = m % LL;
    const float* xr = xz + (size_t)m * LDXZ;
    float s = 0.f;
#pragma unroll
    for (int h = 0; h < 2; h++) {
        int e = (lane << 3) + (h << 2);
        float4 vm = *(const float4*)(xr + e);
        float4 vl = (l > 0) ? *(const float4*)(xr - LDXZ + e) : make_float4(0.f, 0.f, 0.f, 0.f);
        float4 vh = (l < LL - 1) ? *(const float4*)(xr + LDXZ + e) : make_float4(0.f, 0.f, 0.f, 0.f);
        float am[4] = {vm.x, vm.y, vm.z, vm.w};
        float al[4] = {vl.x, vl.y, vl.z, vl.w};
        float ah[4] = {vh.x, vh.y, vh.z, vh.w};
        float out[4];
#pragma unroll
        for (int j = 0; j < 4; j++) {
            int ee = e + j;
            float acc = tf32r(am[j]) * tf32r(cw[ee * 3 + 1]);
            acc += tf32r(al[j]) * tf32r(cw[ee * 3 + 0]);
            acc += tf32r(ah[j]) * tf32r(cw[ee * 3 + 2]);
            acc += cb[ee];
            float sv = acc / (1.f + __expf(-acc));
            out[j] = sv;
            s += sv;
        }
        *(float4*)(xc + (size_t)m * EE + e) = make_float4(out[0], out[1], out[2], out[3]);
    }
    s = wredsum(s);
    if (lane == 0) xsum[m] = s;
}

// Sequential scan with fused softplus/dB. Aj pre-scaled by log2(e):
// exp(clip(d*A,-10,0)) == exp2(max(d*Aj, -10*log2e)); upper clip dead (d>=0, A<0).
// lastonly: emit s only at t = LL-1.
__global__ void __launch_bounds__(256) scan_kernel(
    const float* __restrict__ ssm, const float* __restrict__ xsum,
    const float* __restrict__ A_log, float* __restrict__ sout, int lastonly)
{
    int b = blockIdx.x, tid = threadIdx.x;
    __shared__ float A_sh[SS];
    __shared__ __align__(16) float gbuf[2][SS];
    __shared__ float psum[8];
    if (tid < SS) {
        float al = A_log[tid];
        al = fminf(fmaxf(al, -5.f), 5.f);
        A_sh[tid] = -expf(al) * 1.44269504088896340736f;   // A * log2(e)
        gbuf[0][tid] = 0.f;
    }
    __syncthreads();
    int i = tid >> 2, sub = tid & 3;
    float Aj[16];
#pragma unroll
    for (int q = 0; q < 16; q++) Aj[q] = A_sh[sub * 16 + q];

    const float* row = ssm + (size_t)b * LL * LDSSM;
    const float* xsr = xsum + b * LL;
    float nd = row[i], nbm = row[SS + i], nC = row[2 * SS + i], nxs = xsr[0];
    const float CLMP = -14.4269504088896340736f;           // -10*log2(e)

    for (int t = 0; t < LL; t++) {
        float draw = nd, bm = nbm, Cv = nC, xs = nxs;
        if (t + 1 < LL) {
            const float* r2 = row + (t + 1) * LDSSM;
            nd = r2[i]; nbm = r2[SS + i]; nC = r2[2 * SS + i]; nxs = xsr[t + 1];
        }
        float d = fmaxf(draw, 0.f) + log1pf(__expf(-fabsf(draw)));
        float db = d * bm;
        int par = t & 1;
        const float4* g4 = (const float4*)(gbuf[par] + sub * 16);
        float acc = 0.f;
#pragma unroll
        for (int q4 = 0; q4 < 4; q4++) {
            float4 gv = g4[q4];
            acc += tf32r(exp2f(fmaxf(d * Aj[q4 * 4 + 0], CLMP))) * gv.x;
            acc += tf32r(exp2f(fmaxf(d * Aj[q4 * 4 + 1], CLMP))) * gv.y;
            acc += tf32r(exp2f(fmaxf(d * Aj[q4 * 4 + 2], CLMP))) * gv.z;
            acc += tf32r(exp2f(fmaxf(d * Aj[q4 * 4 + 3], CLMP))) * gv.w;
        }
        acc += __shfl_xor_sync(0xffffffffu, acc, 1);
        acc += __shfl_xor_sync(0xffffffffu, acc, 2);
        int emit = (!lastonly) || (t == LL - 1);
        if (sub == 0) {
            float gn = acc + db * xs;
            gn = fminf(fmaxf(gn, -100.f), 100.f);
            float gr = tf32r(gn);
            gbuf[par ^ 1][i] = gr;
            if (emit) {
                float p = gr * tf32r(Cv);
                p += __shfl_xor_sync(0x11111111u, p, 4);
                p += __shfl_xor_sync(0x11111111u, p, 8);
                p += __shfl_xor_sync(0x11111111u, p, 16);
                if ((tid & 31) == 0) psum[tid >> 5] = p;
            }
        }
        __syncthreads();
        if (emit && tid == 0) {
            float t2 = 0.f;
#pragma unroll
            for (int w = 0; w < 8; w++) t2 += psum[w];
            sout[b * LL + t] = t2;
        }
    }
}

// y = s + D*x ; inner LN over E (two-pass); y *= silu(z). Warp per row, 8 rows/CTA.
__global__ void __launch_bounds__(256) act_kernel(
    const float* __restrict__ xc, const float* __restrict__ s_in,
    const float* __restrict__ xz, const float* __restrict__ D,
    const float* __restrict__ ig, const float* __restrict__ ib,
    float* __restrict__ y, int lastonly) {
    int warp = threadIdx.x >> 5, lane = threadIdx.x & 31;
    int r = blockIdx.x * 8 + warp;
    int m = lastonly ? (r * LL + (LL - 1)) : r;
    float sv = s_in[m];
    const float* xcr = xc + (size_t)m * EE;
    float yv[8];
    float tot = 0.f;
#pragma unroll
    for (int h = 0; h < 2; h++) {
        int e = (lane << 3) + (h << 2);
        float4 xv = *(const float4*)(xcr + e);
        float4 dv = *(const float4*)(D + e);
        yv[h * 4 + 0] = sv + dv.x * xv.x; yv[h * 4 + 1] = sv + dv.y * xv.y;
        yv[h * 4 + 2] = sv + dv.z * xv.z; yv[h * 4 + 3] = sv + dv.w * xv.w;
        tot += yv[h * 4 + 0] + yv[h * 4 + 1] + yv[h * 4 + 2] + yv[h * 4 + 3];
    }
    float mean = wredsum(tot) * (1.f / EE);
    float vs = 0.f;
#pragma unroll
    for (int q = 0; q < 8; q++) { yv[q] -= mean; vs += yv[q] * yv[q]; }
    float var = wredsum(vs) * (1.f / EE);
    float inv = rsqrtf(var + 1e-5f);
    const float* zr = xz + (size_t)m * LDXZ + EE;
#pragma unroll
    for (int h = 0; h < 2; h++) {
        int e = (lane << 3) + (h << 2);
        float4 gv = *(const float4*)(ig + e);
        float4 bv = *(const float4*)(ib + e);
        float4 zv = *(const float4*)(zr + e);
        float4 o;
        o.x = (yv[h*4+0] * inv * gv.x + bv.x) * (zv.x / (1.f + __expf(-zv.x)));
        o.y = (yv[h*4+1] * inv * gv.y + bv.y) * (zv.y / (1.f + __expf(-zv.y)));
        o.z = (yv[h*4+2] * inv * gv.z + bv.z) * (zv.z / (1.f + __expf(-zv.z)));
        o.w = (yv[h*4+3] * inv * gv.w + bv.w) * (zv.w / (1.f + __expf(-zv.w)));
        *(float4*)(y + (size_t)m * EE + e) = o;
    }
}

// small projection for the last timestep rows only (block-2 z-half / C-cols)
__global__ void lastproj_kernel(const float* __restrict__ A, int lda,
                                const float* __restrict__ W, int ldw,
                                const float* __restrict__ bias,
                                float* __restrict__ C, int ldc,
                                int Kdim, int ncols, int coloff) {
    int b = blockIdx.x;
    int row = b * LL + (LL - 1);
    __shared__ float ush[EE];
    int tid = threadIdx.x;
    if (tid < Kdim) ush[tid] = tf32r(A[(size_t)row * lda + tid]);
    __syncthreads();
    for (int n = tid; n < ncols; n += blockDim.x) {
        float acc = 0.f;
        const float* wp = W + coloff + n;
#pragma unroll 4
        for (int k = 0; k < Kdim; k++) acc += ush[k] * tf32r(wp[(size_t)k * ldw]);
        C[(size_t)row * ldc + coloff + n] = acc + bias[coloff + n];
    }
}

// out-proj + residual + mask for last timestep rows (block 2)
__global__ void lastout_kernel(const float* __restrict__ y, const float* __restrict__ ow,
                               const float* __restrict__ ob, const int* __restrict__ seqs,
                               float* __restrict__ x) {
    int b = blockIdx.x, h = threadIdx.x;   // 128 threads
    int row = b * LL + (LL - 1);
    __shared__ float ysh[EE];
    ysh[h] = tf32r(y[(size_t)row * EE + h]);
    ysh[h + HH] = tf32r(y[(size_t)row * EE + h + HH]);
    __syncthreads();
    float acc = 0.f;
#pragma unroll 4
    for (int e = 0; e < EE; e++) acc += ysh[e] * tf32r(ow[e * HH + h]);
    float v = x[(size_t)row * HH + h] + (acc + ob[h]);
    x[(size_t)row * HH + h] = (seqs[row] != 0) ? v : 0.f;
}

// final LN (last timestep only, two-pass) + logits vs candidates (tf32 dot)
__global__ void final_kernel(const float* __restrict__ x, const int* __restrict__ idxs,
                             const float* __restrict__ item_emb,
                             const float* __restrict__ fg, const float* __restrict__ fb,
                             float* __restrict__ out) {
    int b = blockIdx.x, tid = threadIdx.x;   // 128 threads
    const float* xr = x + (size_t)(b * LL + LL - 1) * HH;
    float v = xr[tid];
    __shared__ float sh1[4], sh2[4];
    float s1 = v;
#pragma unroll
    for (int o = 16; o; o >>= 1) s1 += __shfl_xor_sync(0xffffffffu, s1, o);
    if ((tid & 31) == 0) sh1[tid >> 5] = s1;
    __syncthreads();
    float mean = (sh1[0] + sh1[1] + sh1[2] + sh1[3]) * (1.f / HH);
    float d = v - mean;
    float s2 = d * d;
#pragma unroll
    for (int o = 16; o; o >>= 1) s2 += __shfl_xor_sync(0xffffffffu, s2, o);
    if ((tid & 31) == 0) sh2[tid >> 5] = s2;
    __syncthreads();
    float var = (sh2[0] + sh2[1] + sh2[2] + sh2[3]) * (1.f / HH);
    __shared__ float xn[HH];
    xn[tid] = tf32r(d * rsqrtf(var + 1e-5f) * fg[tid] + fb[tid]);
    __syncthreads();
    int warp = tid >> 5, lane = tid & 31;
    for (int k = warp; k < KC; k += 4) {
        const float* er = item_emb + (size_t)idxs[b * KC + k] * HH;
        float p = xn[lane] * tf32r(er[lane]) + xn[lane + 32] * tf32r(er[lane + 32])
                + xn[lane + 64] * tf32r(er[lane + 64]) + xn[lane + 96] * tf32r(er[lane + 96]);
#pragma unroll
        for (int o = 16; o; o >>= 1) p += __shfl_xor_sync(0xffffffffu, p, o);
        if (lane == 0) out[b * KC + k] = p;
    }
}

// ---------------------------------------------------------------------------
extern "C" void kernel_launch(void* const* d_in, const int* in_sizes, int n_in,
                              void* d_out, int out_size) {
    (void)in_sizes; (void)n_in; (void)out_size;
    const int*   seqs     = (const int*)d_in[0];
    const int*   idxs     = (const int*)d_in[1];
    const float* item_emb = (const float*)d_in[2];
    const float* pos_emb  = (const float*)d_in[3];
    const float* blk_ln_g = (const float*)d_in[4];
    const float* blk_ln_b = (const float*)d_in[5];
    const float* in_w     = (const float*)d_in[6];
    const float* in_b     = (const float*)d_in[7];
    const float* conv_w   = (const float*)d_in[8];
    const float* conv_b   = (const float*)d_in[9];
    const float* xproj_w  = (const float*)d_in[10];
    const float* xproj_b  = (const float*)d_in[11];
    const float* A_log    = (const float*)d_in[12];
    const float* D_param  = (const float*)d_in[13];
    const float* out_w    = (const float*)d_in[14];
    const float* out_b    = (const float*)d_in[15];
    const float* inner_g  = (const float*)d_in[16];
    const float* inner_b  = (const float*)d_in[17];
    const float* final_g  = (const float*)d_in[18];
    const float* final_b  = (const float*)d_in[19];
    float* outp = (float*)d_out;

    float *px, *pu, *pxz, *pxc, *pssm, *py, *pxsum, *ps;
    cudaGetSymbolAddress((void**)&px, g_x);
    cudaGetSymbolAddress((void**)&pu, g_u);
    cudaGetSymbolAddress((void**)&pxz, g_xz);
    cudaGetSymbolAddress((void**)&pxc, g_xc);
    cudaGetSymbolAddress((void**)&pssm, g_ssm);
    cudaGetSymbolAddress((void**)&py, g_y);
    cudaGetSymbolAddress((void**)&pxsum, g_xsum);
    cudaGetSymbolAddress((void**)&ps, g_s);

    for (int blk = 0; blk < NBLK; blk++) {
        const float* iw  = in_w    + (size_t)blk * HH * 2 * EE;
        const float* ibb = in_b    + blk * 2 * EE;
        const float* cw  = conv_w  + blk * EE * 3;
        const float* cb  = conv_b  + blk * EE;
        const float* xw  = xproj_w + (size_t)blk * EE * 3 * SS;
        const float* xb  = xproj_b + blk * 3 * SS;
        const float* al  = A_log   + blk * SS;
        const float* dp  = D_param + blk * EE;
        const float* ow  = out_w   + (size_t)blk * EE * HH;
        const float* ob  = out_b   + blk * HH;
        const float* ig  = inner_g + blk * EE;
        const float* ibn = inner_b + blk * EE;

        if (blk == 0)
            embed_ln_kernel<<<MM / 8, 256>>>(seqs, item_emb, pos_emb,
                                             blk_ln_g, blk_ln_b, px, pu);
        else
            ln128_kernel<<<MM / 8, 256>>>(px, pu, blk_ln_g + blk * HH,
                                          blk_ln_b + blk * HH);

        int Nin = (blk == 0) ? (2 * EE) : EE;
        gemm_tc_kernel<<<dim3(Nin / 64, MM / 128), 256>>>(pu, HH, iw, 2 * EE, ibb,
                                                          pxz, 2 * EE, HH, 0, nullptr);
        if (blk == 1)
            lastproj_kernel<<<BB, 256>>>(pu, HH, iw, 2 * EE, ibb, pxz, 2 * EE,
                                         HH, EE, EE);

        conv_kernel<<<MM / 8, 256>>>(pxz, cw, cb, pxc, pxsum);

        int Nxp = (blk == 0) ? (3 * SS) : (2 * SS);
        gemm_tc_kernel<<<dim3(Nxp / 64, MM / 128), 256>>>(pxc, EE, xw, 3 * SS, xb,
                                                          pssm, LDSSM, EE, 0, nullptr);
        if (blk == 1)
            lastproj_kernel<<<BB, 256>>>(pxc, EE, xw, 3 * SS, xb, pssm, LDSSM,
                                         EE, SS, 2 * SS);

        scan_kernel<<<BB, 256>>>(pssm, pxsum, al, ps, (blk == 1) ? 1 : 0);

        if (blk == 0) {
            act_kernel<<<MM / 8, 256>>>(pxc, ps, pxz, dp, ig, ibn, py, 0);
            gemm_tc_kernel<<<dim3(HH / 64, MM / 128), 256>>>(py, EE, ow, HH, ob,
                                                             px, HH, EE, 1, seqs);
        } else {
            act_kernel<<<BB / 8, 256>>>(pxc, ps, pxz, dp, ig, ibn, py, 1);
            lastout_kernel<<<BB, HH>>>(py, ow, ob, seqs, px);
        }
    }

    final_kernel<<<BB, HH>>>(px, idxs, item_emb, final_g, final_b, outp);
}